// round 14
// baseline (speedup 1.0000x reference)
#include <cuda_runtime.h>
#include <cuda_bf16.h>
#include <math.h>

// Problem constants
#define BB 32
#define TT 32
#define SS 64
#define HH 512
#define EE 512
#define VV 32000
#define T1 (TT-1)
#define TBV ((size_t)T1*BB*VV)
#define BH (BB*HH)
#define MPAD 1024
#define KX 1536
#define JG 2048
#define NCTA 128
#define WF4 4096000u    // VV*HH/4

// -------- persistent device scratch --------
__device__ float g_h[BH];
__device__ float g_c[BH];
__device__ float g_proj[2048*HH];
__device__ __align__(16) float g_XC[BB*1024];
__device__ float g_GpartA[8*BB*JG];                // combined gates partials (z=8, K=128)
__device__ float g_Gemb[MPAD*JG];
__device__ int   g_argmax[T1*BB];
__device__ float g_logits[T1*BB*VV];
__device__ __align__(16) __nv_bfloat16 g_Wh[(size_t)VV*HH];
__device__ __align__(16) __nv_bfloat16 g_Wl[(size_t)VV*HH];
__device__ __align__(16) __nv_bfloat16 g_Ah[MPAD*HH];   // rows 992..1023 stay 0
__device__ __align__(16) __nv_bfloat16 g_Al[MPAD*HH];
__device__ __align__(16) __nv_bfloat16 g_gWh[JG*KX];
__device__ __align__(16) __nv_bfloat16 g_gWl[JG*KX];
__device__ __align__(16) __nv_bfloat16 g_Xh[BB*KX];
__device__ __align__(16) __nv_bfloat16 g_Xl[BB*KX];
__device__ __align__(16) __nv_bfloat16 g_Eh[MPAD*EE];
__device__ __align__(16) __nv_bfloat16 g_El[MPAD*EE];
__device__ __align__(16) __nv_bfloat16 g_ENh[2048*HH];
__device__ __align__(16) __nv_bfloat16 g_ENl[2048*HH];
__device__ __align__(16) __nv_bfloat16 g_WAh[HH*HH];
__device__ __align__(16) __nv_bfloat16 g_WAl[HH*HH];
__device__ unsigned g_barcnt;

__device__ __forceinline__ float sigf(float x){ return 1.0f/(1.0f+expf(-x)); }

__device__ __forceinline__ float fexp(float x){
    float t = x * 1.4426950408889634f;
    float n = rintf(t);
    float f = t - n;
    float p = 1.5403530e-4f;
    p = fmaf(p, f, 1.3333558e-3f);
    p = fmaf(p, f, 9.6181291e-3f);
    p = fmaf(p, f, 5.5504109e-2f);
    p = fmaf(p, f, 2.4022651e-1f);
    p = fmaf(p, f, 6.9314718e-1f);
    p = fmaf(p, f, 1.0f);
    int e = (int)n;
    e = e < -126 ? -126 : (e > 127 ? 127 : e);
    float sc = __int_as_float((e+127)<<23);
    return p*sc;
}

// ------------------ low-level helpers ------------------
__device__ __forceinline__ unsigned smem_u32(const void* p){
    unsigned a;
    asm("{ .reg .u64 t; cvta.to.shared.u64 t, %1; cvt.u32.u64 %0, t; }" : "=r"(a) : "l"(p));
    return a;
}
__device__ __forceinline__ void cpa16(unsigned dst, const void* src){
    asm volatile("cp.async.cg.shared.global [%0], [%1], 16;" :: "r"(dst), "l"(src));
}
#define CP_COMMIT() asm volatile("cp.async.commit_group;" ::: "memory")
#define CP_WAIT(n)  asm volatile("cp.async.wait_group %0;" :: "n"(n) : "memory")

__device__ __forceinline__ void ldmx4(unsigned* r, unsigned addr){
    asm volatile("ldmatrix.sync.aligned.m8n8.x4.shared.b16 {%0,%1,%2,%3}, [%4];"
        : "=r"(r[0]), "=r"(r[1]), "=r"(r[2]), "=r"(r[3]) : "r"(addr));
}
__device__ __forceinline__ void mma16816(float* d, const unsigned* a,
                                         unsigned b0, unsigned b1){
    asm volatile(
        "mma.sync.aligned.m16n8k16.row.col.f32.bf16.bf16.f32 "
        "{%0,%1,%2,%3}, {%4,%5,%6,%7}, {%8,%9}, {%0,%1,%2,%3};"
        : "+f"(d[0]), "+f"(d[1]), "+f"(d[2]), "+f"(d[3])
        : "r"(a[0]), "r"(a[1]), "r"(a[2]), "r"(a[3]), "r"(b0), "r"(b1));
}
__device__ __forceinline__ void bsplit(float v, __nv_bfloat16& hi, __nv_bfloat16& lo){
    hi = __float2bfloat16(v);
    lo = __float2bfloat16(v - __bfloat162float(hi));
}

// PROVEN R10 spin grid barrier: sc-fence + atomicAdd arrive, acquire poll.
__device__ __forceinline__ void gbar(unsigned target){
    __syncthreads();
    if (threadIdx.x == 0){
        __threadfence();
        atomicAdd(&g_barcnt, 1u);
        unsigned v;
        do {
            asm volatile("ld.global.acquire.gpu.b32 %0, [%1];"
                         : "=r"(v) : "l"(&g_barcnt));
        } while (v < target);
    }
    __syncthreads();
}

// ---------------------------------------------------------------------------
// Prologue: h,c init + X (ah=0, h=h0) + barrier reset
// ---------------------------------------------------------------------------
__global__ void k_prep0(const float* __restrict__ h0, const float* __restrict__ c0)
{
    if (blockIdx.x == 0 && threadIdx.x == 0) g_barcnt = 0;
    int idx = blockIdx.x*256 + threadIdx.x;
    int b = idx >> 9, k = idx & 511;
    g_h[idx] = h0[idx];
    g_c[idx] = c0[idx];
    __nv_bfloat16 hi, lo;
    g_Xh[b*KX + 512 + k] = __float2bfloat16(0.f);
    g_Xl[b*KX + 512 + k] = __float2bfloat16(0.f);
    bsplit(h0[idx], hi, lo);
    g_Xh[b*KX + 1024 + k] = hi;  g_Xl[b*KX + 1024 + k] = lo;
}

// ---------------------------------------------------------------------------
// Merged conversion prologue (R13-proven partition):
//  [0,512) emb gather | [512,3584) gate weights | [3584,4864) enc + W_a
// ---------------------------------------------------------------------------
__global__ void k_convall(const int* __restrict__ tgt, const float* __restrict__ emb,
                          const float* __restrict__ W_ih, const float* __restrict__ W_hh,
                          const float* __restrict__ enc, const float* __restrict__ W_a)
{
    const int blk = blockIdx.x;
    if (blk < 512){
        int i = (blk*256 + threadIdx.x)*4;
        int r = i >> 9, k = i & 511;
        float4 v = make_float4(0.f,0.f,0.f,0.f);
        if (r < T1*BB){
            int t = r >> 5, b = r & 31;
            int w = tgt[b*TT + t];
            v = *(const float4*)(emb + (size_t)w*EE + k);
        }
        __nv_bfloat16 h0,h1,h2,h3,l0,l1,l2,l3;
        bsplit(v.x,h0,l0); bsplit(v.y,h1,l1); bsplit(v.z,h2,l2); bsplit(v.w,h3,l3);
        *(__nv_bfloat162*)(g_Eh + i)     = __nv_bfloat162(h0,h1);
        *(__nv_bfloat162*)(g_Eh + i + 2) = __nv_bfloat162(h2,h3);
        *(__nv_bfloat162*)(g_El + i)     = __nv_bfloat162(l0,l1);
        *(__nv_bfloat162*)(g_El + i + 2) = __nv_bfloat162(l2,l3);
    } else if (blk < 3584){
        size_t i = ((size_t)(blk-512)*256 + threadIdx.x)*4;
        if (i >= (size_t)JG*KX) return;
        int j = (int)(i / KX);
        int k = (int)(i % KX);
        float4 v = (k < 1024) ? *(const float4*)(W_ih + (size_t)j*1024 + k)
                              : *(const float4*)(W_hh + (size_t)j*512 + (k-1024));
        __nv_bfloat16 h, l;
        bsplit(v.x, h, l); g_gWh[i+0]=h; g_gWl[i+0]=l;
        bsplit(v.y, h, l); g_gWh[i+1]=h; g_gWl[i+1]=l;
        bsplit(v.z, h, l); g_gWh[i+2]=h; g_gWl[i+2]=l;
        bsplit(v.w, h, l); g_gWh[i+3]=h; g_gWl[i+3]=l;
    } else {
        size_t i = ((size_t)(blk-3584)*256 + threadIdx.x)*4;
        const size_t NE = (size_t)2048*HH;
        if (i >= NE + (size_t)HH*HH) return;
        const float* src; __nv_bfloat16 *dh, *dl; size_t off;
        if (i < NE){ src = enc;  dh = g_ENh; dl = g_ENl; off = i; }
        else       { src = W_a;  dh = g_WAh; dl = g_WAl; off = i - NE; }
        float4 v = *(const float4*)(src + off);
        __nv_bfloat16 h0,h1,h2,h3,l0,l1,l2,l3;
        bsplit(v.x,h0,l0); bsplit(v.y,h1,l1); bsplit(v.z,h2,l2); bsplit(v.w,h3,l3);
        *(__nv_bfloat162*)(dh + off)     = __nv_bfloat162(h0,h1);
        *(__nv_bfloat162*)(dh + off + 2) = __nv_bfloat162(h2,h3);
        *(__nv_bfloat162*)(dl + off)     = __nv_bfloat162(l0,l1);
        *(__nv_bfloat162*)(dl + off + 2) = __nv_bfloat162(l2,l3);
    }
}

// ---------------------------------------------------------------------------
// Generic HMMA GEMM (prologue: Gemb, proj) — now fragment-pipelined like k_vocab
// ---------------------------------------------------------------------------
#define VK_STR 40

__global__ void __launch_bounds__(256, 2)
k_hmm(const __nv_bfloat16* __restrict__ Ah, const __nv_bfloat16* __restrict__ Al, int lda,
      const __nv_bfloat16* __restrict__ Bh, const __nv_bfloat16* __restrict__ Bl, int ldb,
      float* __restrict__ C, int ldc,
      const float* __restrict__ bias1, const float* __restrict__ bias2)
{
    extern __shared__ char vsm[];
    const int tid  = threadIdx.x;
    const int wid  = tid >> 5, lane = tid & 31;
    const int mtile = blockIdx.x;
    const int ntile = blockIdx.y;

    const __nv_bfloat16* Asrc_h = Ah + (size_t)mtile*128*lda;
    const __nv_bfloat16* Asrc_l = Al + (size_t)mtile*128*lda;
    const __nv_bfloat16* Bsrc_h = Bh + (size_t)ntile*64*ldb;
    const __nv_bfloat16* Bsrc_l = Bl + (size_t)ntile*64*ldb;

    const unsigned base = smem_u32(vsm);
    const unsigned uAh = base;
    const unsigned uAl = base + 20480;
    const unsigned uBh = base + 40960;
    const unsigned uBl = base + 51200;

    auto issue = [&](int buf, int ch){
        const int k0 = ch*32;
        const unsigned a_h = uAh + buf*10240;
        const unsigned a_l = uAl + buf*10240;
        const unsigned b_h = uBh + buf*5120;
        const unsigned b_l = uBl + buf*5120;
        #pragma unroll
        for (int q = 0; q < 6; q++){
            int i = q*256 + tid;
            if (i < 1024){
                int j = i & 511; int r = j >> 2, c8 = (j & 3)*8;
                const __nv_bfloat16* src = (i < 512 ? Asrc_h : Asrc_l)
                                           + (size_t)r*lda + k0 + c8;
                unsigned dst = (i < 512 ? a_h : a_l) + (unsigned)(r*VK_STR + c8)*2;
                cpa16(dst, src);
            } else {
                int j = (i - 1024) & 255; int r = j >> 2, c8 = (j & 3)*8;
                const __nv_bfloat16* src = (i < 1280 ? Bsrc_h : Bsrc_l)
                                           + (size_t)r*ldb + k0 + c8;
                unsigned dst = (i < 1280 ? b_h : b_l) + (unsigned)(r*VK_STR + c8)*2;
                cpa16(dst, src);
            }
        }
    };

    float acc[2][4][4];
    #pragma unroll
    for (int mi=0;mi<2;mi++)
        #pragma unroll
        for (int ni=0;ni<4;ni++)
            #pragma unroll
            for (int q=0;q<4;q++) acc[mi][ni][q]=0.f;

    const int m0 = (wid & 3) * 32;
    const int n0 = (wid >> 2) * 32;
    const int arow  = (lane & 7) + ((lane >> 3) & 1) * 8;
    const int akoff = (lane >> 4) * 8;
    const int brow  = (lane & 7) + ((lane >> 4) & 1) * 8;
    const int bkoff = ((lane >> 3) & 1) * 8;

    issue(0, 0); CP_COMMIT();
    const int NCH = 16;
    for (int ch = 0; ch < NCH; ch++){
        int buf = ch & 1;
        if (ch + 1 < NCH){ issue(buf ^ 1, ch + 1); CP_COMMIT(); CP_WAIT(1); }
        else             { CP_WAIT(0); }
        __syncthreads();
        const unsigned a_h = uAh + buf*10240;
        const unsigned a_l = uAl + buf*10240;
        const unsigned b_h = uBh + buf*5120;
        const unsigned b_l = uBl + buf*5120;

        unsigned afh[2][2][4], afl[2][2][4], bfh[2][2][4], bfl[2][2][4];
        #pragma unroll
        for (int s2 = 0; s2 < 2; s2++){
            const int ks = s2*16;
            #pragma unroll
            for (int mi=0;mi<2;mi++){
                ldmx4(afh[s2][mi], a_h + (unsigned)((m0 + mi*16 + arow)*VK_STR + ks + akoff)*2);
                ldmx4(afl[s2][mi], a_l + (unsigned)((m0 + mi*16 + arow)*VK_STR + ks + akoff)*2);
            }
            #pragma unroll
            for (int g=0; g<2; g++){
                ldmx4(bfh[s2][g], b_h + (unsigned)((n0 + g*16 + brow)*VK_STR + ks + bkoff)*2);
                ldmx4(bfl[s2][g], b_l + (unsigned)((n0 + g*16 + brow)*VK_STR + ks + bkoff)*2);
            }
        }
        #pragma unroll
        for (int s2 = 0; s2 < 2; s2++)
            #pragma unroll
            for (int mi=0;mi<2;mi++)
                #pragma unroll
                for (int ni=0;ni<4;ni++){
                    unsigned h0 = bfh[s2][ni>>1][(ni&1)*2], h1 = bfh[s2][ni>>1][(ni&1)*2+1];
                    unsigned l0 = bfl[s2][ni>>1][(ni&1)*2], l1 = bfl[s2][ni>>1][(ni&1)*2+1];
                    mma16816(acc[mi][ni], afh[s2][mi], h0, h1);
                    mma16816(acc[mi][ni], afh[s2][mi], l0, l1);
                    mma16816(acc[mi][ni], afl[s2][mi], h0, h1);
                }
        __syncthreads();
    }

    #pragma unroll
    for (int mi=0;mi<2;mi++){
        #pragma unroll
        for (int ni=0;ni<4;ni++){
            int row = mtile*128 + m0 + mi*16 + (lane >> 2);
            int col = ntile*64  + n0 + ni*8  + (lane & 3)*2;
            float bia0 = 0.f, bia1 = 0.f;
            if (bias1){ bia0 += bias1[col]; bia1 += bias1[col+1]; }
            if (bias2){ bia0 += bias2[col]; bia1 += bias2[col+1]; }
            float* o = C + (size_t)row*ldc + col;
            o[0] = acc[mi][ni][0] + bia0;
            o[1] = acc[mi][ni][1] + bia1;
            o += 8*ldc;
            o[0] = acc[mi][ni][2] + bia0;
            o[1] = acc[mi][ni][3] + bia1;
        }
    }
}

// ---------------------------------------------------------------------------
// convW slice (in-loop idle CTAs)
// ---------------------------------------------------------------------------
__device__ __forceinline__ void convW_item(const float* __restrict__ W, unsigned i4)
{
    size_t i = (size_t)i4 * 4;
    float4 v = *(const float4*)(W + i);
    __nv_bfloat16 h0, h1, h2, h3, l0, l1, l2, l3;
    bsplit(v.x, h0, l0); bsplit(v.y, h1, l1);
    bsplit(v.z, h2, l2); bsplit(v.w, h3, l3);
    *(__nv_bfloat162*)(g_Wh + i)     = __nv_bfloat162(h0, h1);
    *(__nv_bfloat162*)(g_Wh + i + 2) = __nv_bfloat162(h2, h3);
    *(__nv_bfloat162*)(g_Wl + i)     = __nv_bfloat162(l0, l1);
    *(__nv_bfloat162*)(g_Wl + i + 2) = __nv_bfloat162(l2, l3);
}

// ---------------------------------------------------------------------------
// Persistent recurrent loop. NEW layout:
//  Phase A: COMBINED gates (ah+h, K=128/CTA over [512,1536)), weights resident
//  Phase B: cell+attn (0..31) | convW (32..127)
//  Phase C: ah2 only (0..63)
// smem (157696B): [0,73728) resident gate weights (2 chunks x 36864)
//                 [73728,139264) XC staging (CTAs<64, phase C)
//                 [139264,157696) scratch: A-tiles 2x9216 / phase-B hh+sc
// ---------------------------------------------------------------------------
#define GSTR 72
#define OFF_XC  73728
#define OFF_SCR 139264
#define LOOP_SMEM 157696

__global__ void __launch_bounds__(256)
k_loop(const int* __restrict__ lens, const float* __restrict__ enc,
       const float* __restrict__ W_c, const float* __restrict__ b_c,
       const float* __restrict__ W_o)
{
    extern __shared__ char dsm[];
    const int ct  = blockIdx.x;
    const int tid = threadIdx.x;
    const int w = tid >> 5, l = tid & 31;
    const unsigned base = smem_u32(dsm);

    const int nt = ct & 15;
    const int z  = ct >> 4;
    const int nbase = nt * 128;
    const int n0 = w * 16;
    const int arow  = (l & 7) + ((l >> 3) & 1) * 8;
    const int akoff = (l >> 4) * 8;
    const int brow  = (l & 7) + ((l >> 4) & 1) * 8;
    const int bkoff = ((l >> 3) & 1) * 8;

    float wreg[32];
    float wbias = 0.f;
    if (ct < 64){
        const int c = ct*8 + w;
        const float* wr = W_c + (size_t)c*1024;
        #pragma unroll
        for (int q=0;q<32;q++) wreg[q] = wr[l + q*32];
        wbias = b_c[c];
    }

    // pre-stage resident combined-gates weights: K slice [512+z*128, 512+(z+1)*128)
    {
        #pragma unroll
        for (int ck = 0; ck < 2; ck++){
            const int koff = 512 + z*128 + ck*64;
            #pragma unroll
            for (int q = 0; q < 8; q++){
                int i = q*256 + tid;
                int idx = i & 1023; int row = idx >> 3, c8 = idx & 7;
                const __nv_bfloat16* src = (i < 1024 ? g_gWh : g_gWl)
                                           + (size_t)(nbase+row)*KX + koff + c8*8;
                unsigned dst = base + (unsigned)ck*36864u
                             + (i < 1024 ? 0u : 18432u)
                             + (unsigned)(row*GSTR + c8*8)*2;
                cpa16(dst, src);
            }
        }
        CP_COMMIT(); CP_WAIT(0);
        __syncthreads();
    }

    unsigned nb = 0;

    for (int t = 0; t < T1; t++){
        // ===== Phase A: combined gates (all CTAs, 2 chunks, resident weights) =====
        {
            auto issueA = [&](int buf, int ck){
                const int koff = 512 + z*128 + ck*64;
                const unsigned uAh = base + OFF_SCR + (unsigned)buf*9216u;
                const unsigned uAl = uAh + 4608;
                #pragma unroll
                for (int q = 0; q < 2; q++){
                    int i = q*256 + tid;
                    int idx = i & 255; int row = idx >> 3, c8 = idx & 7;
                    const __nv_bfloat16* src = (i < 256 ? g_Xh : g_Xl)
                                               + (size_t)row*KX + koff + c8*8;
                    unsigned dst = (i < 256 ? uAh : uAl) + (unsigned)(row*GSTR + c8*8)*2;
                    cpa16(dst, src);
                }
            };

            float acc[2][2][4];
            #pragma unroll
            for (int mi=0;mi<2;mi++)
                #pragma unroll
                for (int ni=0;ni<2;ni++)
                    #pragma unroll
                    for (int q=0;q<4;q++) acc[mi][ni][q]=0.f;

            issueA(0, 0); CP_COMMIT();
            #pragma unroll
            for (int ck = 0; ck < 2; ck++){
                if (ck == 0){ issueA(1, 1); CP_COMMIT(); CP_WAIT(1); }
                else        { CP_WAIT(0); }
                __syncthreads();
                const unsigned uAh = base + OFF_SCR + (unsigned)ck*9216u;
                const unsigned uAl = uAh + 4608;
                const unsigned uBh = base + (unsigned)ck*36864u;
                const unsigned uBl = uBh + 18432;
                #pragma unroll
                for (int ks = 0; ks < 64; ks += 16){
                    unsigned afh[2][4], afl[2][4], bfh[4], bfl[4];
                    #pragma unroll
                    for (int mi=0;mi<2;mi++){
                        ldmx4(afh[mi], uAh + (unsigned)((mi*16 + arow)*GSTR + ks + akoff)*2);
                        ldmx4(afl[mi], uAl + (unsigned)((mi*16 + arow)*GSTR + ks + akoff)*2);
                    }
                    ldmx4(bfh, uBh + (unsigned)((n0 + brow)*GSTR + ks + bkoff)*2);
                    ldmx4(bfl, uBl + (unsigned)((n0 + brow)*GSTR + ks + bkoff)*2);
                    #pragma unroll
                    for (int mi=0;mi<2;mi++)
                        #pragma unroll
                        for (int ni=0;ni<2;ni++){
                            mma16816(acc[mi][ni], afh[mi], bfh[ni*2], bfh[ni*2+1]);
                            mma16816(acc[mi][ni], afh[mi], bfl[ni*2], bfl[ni*2+1]);
                            mma16816(acc[mi][ni], afl[mi], bfh[ni*2], bfh[ni*2+1]);
                        }
                }
                __syncthreads();
            }

            #pragma unroll
            for (int mi=0;mi<2;mi++){
                #pragma unroll
                for (int ni=0;ni<2;ni++){
                    int row = mi*16 + (l >> 2);
                    int col = nbase + n0 + ni*8 + (l & 3)*2;
                    float* gp = g_GpartA + ((size_t)z*BB + row)*JG + col;
                    gp[0] = acc[mi][ni][0];
                    gp[1] = acc[mi][ni][1];
                    gp += 8*JG;
                    gp[0] = acc[mi][ni][2];
                    gp[1] = acc[mi][ni][3];
                }
            }
        }
        gbar(++nb * NCTA);

        // ===== Phase B: cell+attn (0..31) | convW (32..127) =====
        if (ct < BB){
            const int b = ct;
            float* hh = (float*)(dsm + OFF_SCR);
            float* sc = hh + HH;
            const int len = lens[b];

            #pragma unroll
            for (int rep = 0; rep < 2; rep++){
                int h = tid + rep*256;
                float gv[4];
                #pragma unroll
                for (int q=0;q<4;q++){
                    int j = q*HH + h;
                    float s = g_Gemb[((size_t)t*BB + b)*JG + j];
                    #pragma unroll
                    for (int zz=0;zz<8;zz++) s += g_GpartA[((size_t)zz*BB + b)*JG + j];
                    gv[q] = s;
                }
                int idx = b*HH + h;
                float ig = sigf(gv[0]);
                float fg = sigf(gv[1]);
                float gg = tanhf(gv[2]);
                float og = sigf(gv[3]);
                float c  = fg * g_c[idx] + ig * gg;
                g_c[idx] = c;
                float h2 = og * tanhf(c);
                g_h[idx] = h2;
                hh[h] = h2;
                g_XC[b*1024 + h] = h2;
                __nv_bfloat16 hi, lo; bsplit(h2, hi, lo);
                g_Xh[b*KX + 1024 + h] = hi;
                g_Xl[b*KX + 1024 + h] = lo;
            }
            __syncthreads();

            #pragma unroll
            for (int i = 0; i < 8; i++){
                int s = w*8 + i;
                const float* pr = &g_proj[((size_t)s*BB + b)*HH];
                float sum = 0.f;
                #pragma unroll
                for (int k = 0; k < 16; k++) sum += hh[l + k*32] * pr[l + k*32];
                #pragma unroll
                for (int off=16; off>0; off>>=1) sum += __shfl_xor_sync(0xffffffffu, sum, off);
                if (l == 0) sc[s] = (s < len) ? sum : -1e9f;
            }
            __syncthreads();

            if (tid < 32){
                float v0 = sc[tid], v1 = sc[tid+32];
                float m = fmaxf(v0, v1);
                #pragma unroll
                for (int off=16; off>0; off>>=1) m = fmaxf(m, __shfl_xor_sync(0xffffffffu, m, off));
                float e0 = expf(v0 - m), e1 = expf(v1 - m);
                float s = e0 + e1;
                #pragma unroll
                for (int off=16; off>0; off>>=1) s += __shfl_xor_sync(0xffffffffu, s, off);
                float inv = 1.0f / s;
                sc[tid]    = e0 * inv;
                sc[tid+32] = e1 * inv;
            }
            __syncthreads();

            #pragma unroll
            for (int rep = 0; rep < 2; rep++){
                int h = tid + rep*256;
                float a0=0.f, a1=0.f, a2=0.f, a3=0.f;
                #pragma unroll 4
                for (int s0 = 0; s0 < 16; s0++){
                    a0 += sc[s0]      * enc[((size_t)(s0)*BB    + b)*HH + h];
                    a1 += sc[s0 + 16] * enc[((size_t)(s0+16)*BB + b)*HH + h];
                    a2 += sc[s0 + 32] * enc[((size_t)(s0+32)*BB + b)*HH + h];
                    a3 += sc[s0 + 48] * enc[((size_t)(s0+48)*BB + b)*HH + h];
                }
                g_XC[b*1024 + 512 + h] = (a0 + a1) + (a2 + a3);
            }
        } else {
            unsigned winbase = (unsigned)t * 147456u;
            #pragma unroll
            for (int j = 0; j < 6; j++){
                unsigned i4 = winbase + (unsigned)j*24576u + (unsigned)(ct-32)*256u + tid;
                if (i4 < WF4) convW_item(W_o, i4);
            }
        }
        gbar(++nb * NCTA);

        // ===== Phase C: ah2 only (CTAs 0..63) =====
        if (ct < 64){
            float* xc = (float*)(dsm + OFF_XC);
            const int c = ct*8 + w;
            #pragma unroll
            for (int half = 0; half < 2; half++){
                if (half) __syncthreads();
                {
                    const float4* src = (const float4*)(g_XC + half*16*1024);
                    float4* dst = (float4*)xc;
                    #pragma unroll
                    for (int i = 0; i < 16; i++) dst[tid + i*256] = src[tid + i*256];
                }
                __syncthreads();
                for (int b = 0; b < 16; b++){
                    const float* xb = xc + b*1024;
                    float s = 0.f;
                    #pragma unroll
                    for (int q=0;q<32;q++) s += wreg[q] * xb[l + q*32];
                    #pragma unroll
                    for (int off=16; off>0; off>>=1) s += __shfl_xor_sync(0xffffffffu, s, off);
                    if (l == 0){
                        int gb = half*16 + b;
                        float v = tanhf(s + wbias);
                        __nv_bfloat16 hi, lo; bsplit(v, hi, lo);
                        int r = t*BB + gb;
                        g_Ah[(size_t)r*HH + c] = hi;
                        g_Al[(size_t)r*HH + c] = lo;
                        g_Xh[gb*KX + 512 + c] = hi;
                        g_Xl[gb*KX + 512 + c] = lo;
                    }
                }
            }
        }
        gbar(++nb * NCTA);
    }
}

// ---------------------------------------------------------------------------
// Vocab GEMM: single K-pass 3-term, software-pipelined fragments (R13-proven)
// ---------------------------------------------------------------------------
__global__ void __launch_bounds__(256, 2)
k_vocab(const float* __restrict__ b_o, float* __restrict__ logits)
{
    extern __shared__ char vsm[];
    const int tid  = threadIdx.x;
    const int wid  = tid >> 5, lane = tid & 31;
    const int mtile = blockIdx.x;
    const int ntile = blockIdx.y;

    const __nv_bfloat16* Asrc_h = g_Ah + (size_t)mtile*128*HH;
    const __nv_bfloat16* Asrc_l = g_Al + (size_t)mtile*128*HH;
    const __nv_bfloat16* Bsrc_h = g_Wh + (size_t)ntile*64*HH;
    const __nv_bfloat16* Bsrc_l = g_Wl + (size_t)ntile*64*HH;

    const unsigned base = smem_u32(vsm);
    const unsigned uAh = base;
    const unsigned uAl = base + 20480;
    const unsigned uBh = base + 40960;
    const unsigned uBl = base + 51200;

    auto issue = [&](int buf, int ch){
        const int k0 = ch*32;
        const unsigned a_h = uAh + buf*10240;
        const unsigned a_l = uAl + buf*10240;
        const unsigned b_h = uBh + buf*5120;
        const unsigned b_l = uBl + buf*5120;
        #pragma unroll
        for (int q = 0; q < 6; q++){
            int i = q*256 + tid;
            if (i < 1024){
                int j = i & 511; int r = j >> 2, c8 = (j & 3)*8;
                const __nv_bfloat16* src = (i < 512 ? Asrc_h : Asrc_l)
                                           + (size_t)r*HH + k0 + c8;
                unsigned dst = (i < 512 ? a_h : a_l) + (unsigned)(r*VK_STR + c8)*2;
                cpa16(dst, src);
            } else {
                int j = (i - 1024) & 255; int r = j >> 2, c8 = (j & 3)*8;
                const __nv_bfloat16* src = (i < 1280 ? Bsrc_h : Bsrc_l)
                                           + (size_t)r*HH + k0 + c8;
                unsigned dst = (i < 1280 ? b_h : b_l) + (unsigned)(r*VK_STR + c8)*2;
                cpa16(dst, src);
            }
        }
    };

    float acc[2][4][4];
    #pragma unroll
    for (int mi=0;mi<2;mi++)
        #pragma unroll
        for (int ni=0;ni<4;ni++)
            #pragma unroll
            for (int q=0;q<4;q++) acc[mi][ni][q]=0.f;

    const int m0 = (wid & 3) * 32;
    const int n0 = (wid >> 2) * 32;
    const int arow  = (lane & 7) + ((lane >> 3) & 1) * 8;
    const int akoff = (lane >> 4) * 8;
    const int brow  = (lane & 7) + ((lane >> 4) & 1) * 8;
    const int bkoff = ((lane >> 3) & 1) * 8;

    issue(0, 0); CP_COMMIT();
    const int NCH = 16;
    for (int ch = 0; ch < NCH; ch++){
        int buf = ch & 1;
        if (ch + 1 < NCH){ issue(buf ^ 1, ch + 1); CP_COMMIT(); CP_WAIT(1); }
        else             { CP_WAIT(0); }
        __syncthreads();
        const unsigned a_h = uAh + buf*10240;
        const unsigned a_l = uAl + buf*10240;
        const unsigned b_h = uBh + buf*5120;
        const unsigned b_l = uBl + buf*5120;

        unsigned afh[2][2][4], afl[2][2][4], bfh[2][2][4], bfl[2][2][4];
        #pragma unroll
        for (int s2 = 0; s2 < 2; s2++){
            const int ks = s2*16;
            #pragma unroll
            for (int mi=0;mi<2;mi++){
                ldmx4(afh[s2][mi], a_h + (unsigned)((m0 + mi*16 + arow)*VK_STR + ks + akoff)*2);
                ldmx4(afl[s2][mi], a_l + (unsigned)((m0 + mi*16 + arow)*VK_STR + ks + akoff)*2);
            }
            #pragma unroll
            for (int g=0; g<2; g++){
                ldmx4(bfh[s2][g], b_h + (unsigned)((n0 + g*16 + brow)*VK_STR + ks + bkoff)*2);
                ldmx4(bfl[s2][g], b_l + (unsigned)((n0 + g*16 + brow)*VK_STR + ks + bkoff)*2);
            }
        }
        #pragma unroll
        for (int s2 = 0; s2 < 2; s2++)
            #pragma unroll
            for (int mi=0;mi<2;mi++)
                #pragma unroll
                for (int ni=0;ni<4;ni++){
                    unsigned h0 = bfh[s2][ni>>1][(ni&1)*2], h1 = bfh[s2][ni>>1][(ni&1)*2+1];
                    unsigned l0 = bfl[s2][ni>>1][(ni&1)*2], l1 = bfl[s2][ni>>1][(ni&1)*2+1];
                    mma16816(acc[mi][ni], afh[s2][mi], h0, h1);
                    mma16816(acc[mi][ni], afh[s2][mi], l0, l1);
                    mma16816(acc[mi][ni], afl[s2][mi], h0, h1);
                }
        __syncthreads();
    }

    #pragma unroll
    for (int mi=0;mi<2;mi++){
        #pragma unroll
        for (int ni=0;ni<4;ni++){
            int row = mtile*128 + m0 + mi*16 + (lane >> 2);
            int col = ntile*64  + n0 + ni*8  + (lane & 3)*2;
            float bia0 = b_o[col], bia1 = b_o[col+1];
            if (row < T1*BB){
                float* o = logits + (size_t)row*VV + col;
                o[0] = acc[mi][ni][0] + bia0;
                o[1] = acc[mi][ni][1] + bia1;
            }
            if (row + 8 < T1*BB){
                float* o = logits + (size_t)(row+8)*VV + col;
                o[0] = acc[mi][ni][2] + bia0;
                o[1] = acc[mi][ni][3] + bia1;
            }
        }
    }
}

// ---------------------------------------------------------------------------
// Online log-softmax + argmax : 512 threads, float4 (R13-proven)
// ---------------------------------------------------------------------------
__global__ void __launch_bounds__(512)
k_lsm(float* __restrict__ logits)
{
    __shared__ float ms[512], ss[512];
    __shared__ int   ii[512];
    const int row = blockIdx.x;
    const int tid = threadIdx.x;
    float* x = logits + (size_t)row * VV;
    const float4* x4 = (const float4*)x;
    const int N4 = VV/4;

    float4 v0 = x4[tid];
    float m = v0.x; int mi = tid*4; float s = 1.f;
    {
        float vals[3] = {v0.y, v0.z, v0.w};
        #pragma unroll
        for (int j=0;j<3;j++){
            float v = vals[j];
            if (v > m){ s = s*fexp(m - v) + 1.f; m = v; mi = tid*4 + j + 1; }
            else        s += fexp(v - m);
        }
    }
    for (int i4 = tid + 512; i4 < N4; i4 += 512){
        float4 v4 = x4[i4];
        float vals[4] = {v4.x, v4.y, v4.z, v4.w};
        #pragma unroll
        for (int j=0;j<4;j++){
            float v = vals[j];
            if (v > m){ s = s*fexp(m - v) + 1.f; m = v; mi = i4*4 + j; }
            else        s += fexp(v - m);
        }
    }
    ms[tid]=m; ss[tid]=s; ii[tid]=mi;
    __syncthreads();
    for (int st = 256; st > 0; st >>= 1){
        if (tid < st){
            float m1=ms[tid], s1=ss[tid]; int i1=ii[tid];
            float m2=ms[tid+st], s2=ss[tid+st]; int i2=ii[tid+st];
            if (m2 > m1)      { ms[tid]=m2; ss[tid]=s1*fexp(m1-m2)+s2; ii[tid]=i2; }
            else if (m2 < m1) { ss[tid]=s1+s2*fexp(m2-m1); }
            else              { ss[tid]=s1+s2; ii[tid]=min(i1,i2); }
        }
        __syncthreads();
    }
    float lse = ms[0] + logf(ss[0]);
    if (tid == 0) g_argmax[row] = ii[0];

    float4* xw = (float4*)x;
    for (int i4 = tid; i4 < N4; i4 += 512){
        float4 v4 = xw[i4];
        v4.x -= lse; v4.y -= lse; v4.z -= lse; v4.w -= lse;
        xw[i4] = v4;
    }
}

__global__ void k_tail_f(float* __restrict__ out)
{
    int r = blockIdx.x*blockDim.x + threadIdx.x;
    if (r < T1*BB) out[TBV + r] = (float)g_argmax[r];
}
__global__ void k_tail_i(int* __restrict__ out)
{
    int r = blockIdx.x*blockDim.x + threadIdx.x;
    if (r < T1*BB) out[r] = g_argmax[r];
}

// ---------------------------------------------------------------------------
extern "C" void kernel_launch(void* const* d_in, const int* in_sizes, int n_in,
                              void* d_out, int out_size)
{
    const int*   tgt   = (const int*)  d_in[0];
    const int*   lens  = (const int*)  d_in[1];
    const float* enc   = (const float*)d_in[2];
    const float* h0    = (const float*)d_in[3];
    const float* c0    = (const float*)d_in[4];
    const float* emb   = (const float*)d_in[5];
    const float* W_ih  = (const float*)d_in[6];
    const float* W_hh  = (const float*)d_in[7];
    const float* b_ih  = (const float*)d_in[8];
    const float* b_hh  = (const float*)d_in[9];
    const float* W_a   = (const float*)d_in[10];
    const float* W_c   = (const float*)d_in[11];
    const float* b_c   = (const float*)d_in[12];
    const float* W_o   = (const float*)d_in[13];
    const float* b_o   = (const float*)d_in[14];

    float *p_proj=nullptr, *p_lg=nullptr, *p_gemb=nullptr;
    __nv_bfloat16 *p_eh=nullptr, *p_el=nullptr, *p_gwh=nullptr, *p_gwl=nullptr;
    __nv_bfloat16 *p_enh=nullptr, *p_enl=nullptr, *p_wah=nullptr, *p_wal=nullptr;
    cudaGetSymbolAddress((void**)&p_proj, g_proj);
    cudaGetSymbolAddress((void**)&p_lg,   g_logits);
    cudaGetSymbolAddress((void**)&p_gemb, g_Gemb);
    cudaGetSymbolAddress((void**)&p_eh,   g_Eh);
    cudaGetSymbolAddress((void**)&p_el,   g_El);
    cudaGetSymbolAddress((void**)&p_gwh,  g_gWh);
    cudaGetSymbolAddress((void**)&p_gwl,  g_gWl);
    cudaGetSymbolAddress((void**)&p_enh,  g_ENh);
    cudaGetSymbolAddress((void**)&p_enl,  g_ENl);
    cudaGetSymbolAddress((void**)&p_wah,  g_WAh);
    cudaGetSymbolAddress((void**)&p_wal,  g_WAl);

    const bool big = (size_t)out_size >= TBV;
    float* logits = big ? (float*)d_out : p_lg;

    cudaFuncSetAttribute(k_loop,   cudaFuncAttributeMaxDynamicSharedMemorySize, LOOP_SMEM);
    cudaFuncSetAttribute(k_vocab,  cudaFuncAttributeMaxDynamicSharedMemorySize, 61440);
    cudaFuncSetAttribute(k_hmm,    cudaFuncAttributeMaxDynamicSharedMemorySize, 61440);

    // prologue
    k_prep0<<<64, 256>>>(h0, c0);
    k_convall<<<4864, 256>>>(tgt, emb, W_ih, W_hh, enc, W_a);
    k_hmm<<<dim3(8, 32), 256, 61440>>>(p_eh, p_el, EE, p_gwh, p_gwl, KX,
                                       p_gemb, JG, b_ih, b_hh);
    k_hmm<<<dim3(16, 8), 256, 61440>>>(p_enh, p_enl, HH, p_wah, p_wal, HH,
                                       p_proj, HH, nullptr, nullptr);

    // persistent recurrent loop (combined gates in phase A; no k_gh0 needed)
    k_loop<<<NCTA, 256, LOOP_SMEM>>>(lens, enc, W_c, b_c, W_o);

    // vocab projection + log-softmax
    k_vocab<<<dim3(8, 500), 256, 61440>>>(b_o, logits);
    k_lsm<<<T1*BB, 512>>>(logits);

    if (big && (size_t)out_size >= TBV + (size_t)T1*BB) {
        k_tail_f<<<4, 256>>>((float*)d_out);
    } else if (!big) {
        k_tail_i<<<4, 256>>>((int*)d_out);
    }
}

// round 15
// speedup vs baseline: 1.3238x; 1.3238x over previous
#include <cuda_runtime.h>
#include <cuda_bf16.h>
#include <math.h>

// Problem constants
#define BB 32
#define TT 32
#define SS 64
#define HH 512
#define EE 512
#define VV 32000
#define T1 (TT-1)
#define TBV ((size_t)T1*BB*VV)
#define BH (BB*HH)
#define MPAD 1024
#define KX 1536
#define JG 2048
#define NCTA 128
#define WF4 4096000u    // VV*HH/4

// -------- persistent device scratch --------
__device__ float g_h[BH];
__device__ float g_c[BH];
__device__ float g_proj[2048*HH];
__device__ __align__(16) float g_XC[BB*1024];
__device__ float g_GpartA[8*BB*JG];
__device__ float g_GpartH[4*BB*JG];
__device__ float g_Gemb[MPAD*JG];
__device__ int   g_argmax[T1*BB];
__device__ float g_logits[T1*BB*VV];
__device__ __align__(16) __nv_bfloat16 g_Wh[(size_t)VV*HH];
__device__ __align__(16) __nv_bfloat16 g_Wl[(size_t)VV*HH];
__device__ __align__(16) __nv_bfloat16 g_Ah[MPAD*HH];   // rows 992..1023 stay 0
__device__ __align__(16) __nv_bfloat16 g_Al[MPAD*HH];
__device__ __align__(16) __nv_bfloat16 g_gWh[JG*KX];
__device__ __align__(16) __nv_bfloat16 g_gWl[JG*KX];
__device__ __align__(16) __nv_bfloat16 g_Xh[BB*KX];
__device__ __align__(16) __nv_bfloat16 g_Xl[BB*KX];
__device__ __align__(16) __nv_bfloat16 g_Eh[MPAD*EE];
__device__ __align__(16) __nv_bfloat16 g_El[MPAD*EE];
__device__ __align__(16) __nv_bfloat16 g_ENh[2048*HH];
__device__ __align__(16) __nv_bfloat16 g_ENl[2048*HH];
__device__ __align__(16) __nv_bfloat16 g_WAh[HH*HH];
__device__ __align__(16) __nv_bfloat16 g_WAl[HH*HH];
__device__ unsigned g_barcnt;

__device__ __forceinline__ float sigf(float x){ return 1.0f/(1.0f+expf(-x)); }

__device__ __forceinline__ float fexp(float x){
    float t = x * 1.4426950408889634f;
    float n = rintf(t);
    float f = t - n;
    float p = 1.5403530e-4f;
    p = fmaf(p, f, 1.3333558e-3f);
    p = fmaf(p, f, 9.6181291e-3f);
    p = fmaf(p, f, 5.5504109e-2f);
    p = fmaf(p, f, 2.4022651e-1f);
    p = fmaf(p, f, 6.9314718e-1f);
    p = fmaf(p, f, 1.0f);
    int e = (int)n;
    e = e < -126 ? -126 : (e > 127 ? 127 : e);
    float sc = __int_as_float((e+127)<<23);
    return p*sc;
}

// ------------------ low-level helpers ------------------
__device__ __forceinline__ unsigned smem_u32(const void* p){
    unsigned a;
    asm("{ .reg .u64 t; cvta.to.shared.u64 t, %1; cvt.u32.u64 %0, t; }" : "=r"(a) : "l"(p));
    return a;
}
__device__ __forceinline__ void cpa16(unsigned dst, const void* src){
    asm volatile("cp.async.cg.shared.global [%0], [%1], 16;" :: "r"(dst), "l"(src));
}
#define CP_COMMIT() asm volatile("cp.async.commit_group;" ::: "memory")
#define CP_WAIT(n)  asm volatile("cp.async.wait_group %0;" :: "n"(n) : "memory")

__device__ __forceinline__ void ldmx4(unsigned* r, unsigned addr){
    asm volatile("ldmatrix.sync.aligned.m8n8.x4.shared.b16 {%0,%1,%2,%3}, [%4];"
        : "=r"(r[0]), "=r"(r[1]), "=r"(r[2]), "=r"(r[3]) : "r"(addr));
}
__device__ __forceinline__ void mma16816(float* d, const unsigned* a,
                                         unsigned b0, unsigned b1){
    asm volatile(
        "mma.sync.aligned.m16n8k16.row.col.f32.bf16.bf16.f32 "
        "{%0,%1,%2,%3}, {%4,%5,%6,%7}, {%8,%9}, {%0,%1,%2,%3};"
        : "+f"(d[0]), "+f"(d[1]), "+f"(d[2]), "+f"(d[3])
        : "r"(a[0]), "r"(a[1]), "r"(a[2]), "r"(a[3]), "r"(b0), "r"(b1));
}
__device__ __forceinline__ void bsplit(float v, __nv_bfloat16& hi, __nv_bfloat16& lo){
    hi = __float2bfloat16(v);
    lo = __float2bfloat16(v - __bfloat162float(hi));
}

// PROVEN R10 spin grid barrier: sc-fence + atomicAdd arrive, acquire poll.
__device__ __forceinline__ void gbar(unsigned target){
    __syncthreads();
    if (threadIdx.x == 0){
        __threadfence();
        atomicAdd(&g_barcnt, 1u);
        unsigned v;
        do {
            asm volatile("ld.global.acquire.gpu.b32 %0, [%1];"
                         : "=r"(v) : "l"(&g_barcnt));
        } while (v < target);
    }
    __syncthreads();
}

// ---------------------------------------------------------------------------
// Merged conversion prologue + prep0:
//  [0,512) emb gather | [512,3584) gate weights | [3584,4864) enc + W_a
//  [4864,4928) h/c init + X assembly + barrier reset
// ---------------------------------------------------------------------------
__global__ void k_convall(const int* __restrict__ tgt, const float* __restrict__ emb,
                          const float* __restrict__ W_ih, const float* __restrict__ W_hh,
                          const float* __restrict__ enc, const float* __restrict__ W_a,
                          const float* __restrict__ h0, const float* __restrict__ c0)
{
    const int blk = blockIdx.x;
    if (blk < 512){
        int i = (blk*256 + threadIdx.x)*4;
        int r = i >> 9, k = i & 511;
        float4 v = make_float4(0.f,0.f,0.f,0.f);
        if (r < T1*BB){
            int t = r >> 5, b = r & 31;
            int w = tgt[b*TT + t];
            v = *(const float4*)(emb + (size_t)w*EE + k);
        }
        __nv_bfloat16 h0b,h1,h2,h3,l0,l1,l2,l3;
        bsplit(v.x,h0b,l0); bsplit(v.y,h1,l1); bsplit(v.z,h2,l2); bsplit(v.w,h3,l3);
        *(__nv_bfloat162*)(g_Eh + i)     = __nv_bfloat162(h0b,h1);
        *(__nv_bfloat162*)(g_Eh + i + 2) = __nv_bfloat162(h2,h3);
        *(__nv_bfloat162*)(g_El + i)     = __nv_bfloat162(l0,l1);
        *(__nv_bfloat162*)(g_El + i + 2) = __nv_bfloat162(l2,l3);
    } else if (blk < 3584){
        size_t i = ((size_t)(blk-512)*256 + threadIdx.x)*4;
        if (i >= (size_t)JG*KX) return;
        int j = (int)(i / KX);
        int k = (int)(i % KX);
        float4 v = (k < 1024) ? *(const float4*)(W_ih + (size_t)j*1024 + k)
                              : *(const float4*)(W_hh + (size_t)j*512 + (k-1024));
        __nv_bfloat16 h, l;
        bsplit(v.x, h, l); g_gWh[i+0]=h; g_gWl[i+0]=l;
        bsplit(v.y, h, l); g_gWh[i+1]=h; g_gWl[i+1]=l;
        bsplit(v.z, h, l); g_gWh[i+2]=h; g_gWl[i+2]=l;
        bsplit(v.w, h, l); g_gWh[i+3]=h; g_gWl[i+3]=l;
    } else if (blk < 4864){
        size_t i = ((size_t)(blk-3584)*256 + threadIdx.x)*4;
        const size_t NE = (size_t)2048*HH;
        if (i >= NE + (size_t)HH*HH) return;
        const float* src; __nv_bfloat16 *dh, *dl; size_t off;
        if (i < NE){ src = enc;  dh = g_ENh; dl = g_ENl; off = i; }
        else       { src = W_a;  dh = g_WAh; dl = g_WAl; off = i - NE; }
        float4 v = *(const float4*)(src + off);
        __nv_bfloat16 h0b,h1,h2,h3,l0,l1,l2,l3;
        bsplit(v.x,h0b,l0); bsplit(v.y,h1,l1); bsplit(v.z,h2,l2); bsplit(v.w,h3,l3);
        *(__nv_bfloat162*)(dh + off)     = __nv_bfloat162(h0b,h1);
        *(__nv_bfloat162*)(dh + off + 2) = __nv_bfloat162(h2,h3);
        *(__nv_bfloat162*)(dl + off)     = __nv_bfloat162(l0,l1);
        *(__nv_bfloat162*)(dl + off + 2) = __nv_bfloat162(l2,l3);
    } else {
        // prep0 section
        if (blk == 4864 && threadIdx.x == 0) g_barcnt = 0;
        int idx = (blk-4864)*256 + threadIdx.x;
        int b = idx >> 9, k = idx & 511;
        g_h[idx] = h0[idx];
        g_c[idx] = c0[idx];
        __nv_bfloat16 hi, lo;
        g_Xh[b*KX + 512 + k] = __float2bfloat16(0.f);
        g_Xl[b*KX + 512 + k] = __float2bfloat16(0.f);
        bsplit(h0[idx], hi, lo);
        g_Xh[b*KX + 1024 + k] = hi;  g_Xl[b*KX + 1024 + k] = lo;
    }
}

// ---------------------------------------------------------------------------
// HMMA GEMM body (R13-proven) + dispatcher merging Gemb and proj jobs
// ---------------------------------------------------------------------------
#define VK_STR 40

__device__ __forceinline__ void hmm_body(
    int mtile, int ntile, char* vsm,
    const __nv_bfloat16* __restrict__ Ah, const __nv_bfloat16* __restrict__ Al, int lda,
    const __nv_bfloat16* __restrict__ Bh, const __nv_bfloat16* __restrict__ Bl, int ldb,
    float* __restrict__ C, int ldc,
    const float* __restrict__ bias1, const float* __restrict__ bias2)
{
    const int tid  = threadIdx.x;
    const int wid  = tid >> 5, lane = tid & 31;

    const __nv_bfloat16* Asrc_h = Ah + (size_t)mtile*128*lda;
    const __nv_bfloat16* Asrc_l = Al + (size_t)mtile*128*lda;
    const __nv_bfloat16* Bsrc_h = Bh + (size_t)ntile*64*ldb;
    const __nv_bfloat16* Bsrc_l = Bl + (size_t)ntile*64*ldb;

    const unsigned base = smem_u32(vsm);
    const unsigned uAh = base;
    const unsigned uAl = base + 20480;
    const unsigned uBh = base + 40960;
    const unsigned uBl = base + 51200;

    auto issue = [&](int buf, int ch){
        const int k0 = ch*32;
        const unsigned a_h = uAh + buf*10240;
        const unsigned a_l = uAl + buf*10240;
        const unsigned b_h = uBh + buf*5120;
        const unsigned b_l = uBl + buf*5120;
        #pragma unroll
        for (int q = 0; q < 6; q++){
            int i = q*256 + tid;
            if (i < 1024){
                int j = i & 511; int r = j >> 2, c8 = (j & 3)*8;
                const __nv_bfloat16* src = (i < 512 ? Asrc_h : Asrc_l)
                                           + (size_t)r*lda + k0 + c8;
                unsigned dst = (i < 512 ? a_h : a_l) + (unsigned)(r*VK_STR + c8)*2;
                cpa16(dst, src);
            } else {
                int j = (i - 1024) & 255; int r = j >> 2, c8 = (j & 3)*8;
                const __nv_bfloat16* src = (i < 1280 ? Bsrc_h : Bsrc_l)
                                           + (size_t)r*ldb + k0 + c8;
                unsigned dst = (i < 1280 ? b_h : b_l) + (unsigned)(r*VK_STR + c8)*2;
                cpa16(dst, src);
            }
        }
    };

    float acc[2][4][4];
    #pragma unroll
    for (int mi=0;mi<2;mi++)
        #pragma unroll
        for (int ni=0;ni<4;ni++)
            #pragma unroll
            for (int q=0;q<4;q++) acc[mi][ni][q]=0.f;

    const int m0 = (wid & 3) * 32;
    const int n0 = (wid >> 2) * 32;
    const int arow  = (lane & 7) + ((lane >> 3) & 1) * 8;
    const int akoff = (lane >> 4) * 8;
    const int brow  = (lane & 7) + ((lane >> 4) & 1) * 8;
    const int bkoff = ((lane >> 3) & 1) * 8;

    issue(0, 0); CP_COMMIT();
    const int NCH = 16;
    for (int ch = 0; ch < NCH; ch++){
        int buf = ch & 1;
        if (ch + 1 < NCH){ issue(buf ^ 1, ch + 1); CP_COMMIT(); CP_WAIT(1); }
        else             { CP_WAIT(0); }
        __syncthreads();
        const unsigned a_h = uAh + buf*10240;
        const unsigned a_l = uAl + buf*10240;
        const unsigned b_h = uBh + buf*5120;
        const unsigned b_l = uBl + buf*5120;
        #pragma unroll
        for (int ks = 0; ks < 32; ks += 16){
            unsigned afh[2][4], afl[2][4], bfh[2][4], bfl[2][4];
            #pragma unroll
            for (int mi=0;mi<2;mi++){
                ldmx4(afh[mi], a_h + (unsigned)((m0 + mi*16 + arow)*VK_STR + ks + akoff)*2);
                ldmx4(afl[mi], a_l + (unsigned)((m0 + mi*16 + arow)*VK_STR + ks + akoff)*2);
            }
            #pragma unroll
            for (int g=0; g<2; g++){
                ldmx4(bfh[g], b_h + (unsigned)((n0 + g*16 + brow)*VK_STR + ks + bkoff)*2);
                ldmx4(bfl[g], b_l + (unsigned)((n0 + g*16 + brow)*VK_STR + ks + bkoff)*2);
            }
            #pragma unroll
            for (int mi=0;mi<2;mi++)
                #pragma unroll
                for (int ni=0;ni<4;ni++){
                    unsigned h0 = bfh[ni>>1][(ni&1)*2], h1 = bfh[ni>>1][(ni&1)*2+1];
                    unsigned l0 = bfl[ni>>1][(ni&1)*2], l1 = bfl[ni>>1][(ni&1)*2+1];
                    mma16816(acc[mi][ni], afh[mi], h0, h1);
                    mma16816(acc[mi][ni], afh[mi], l0, l1);
                    mma16816(acc[mi][ni], afl[mi], h0, h1);
                }
        }
        __syncthreads();
    }

    #pragma unroll
    for (int mi=0;mi<2;mi++){
        #pragma unroll
        for (int ni=0;ni<4;ni++){
            int row = mtile*128 + m0 + mi*16 + (lane >> 2);
            int col = ntile*64  + n0 + ni*8  + (lane & 3)*2;
            float bia0 = 0.f, bia1 = 0.f;
            if (bias1){ bia0 += bias1[col]; bia1 += bias1[col+1]; }
            if (bias2){ bia0 += bias2[col]; bia1 += bias2[col+1]; }
            float* o = C + (size_t)row*ldc + col;
            o[0] = acc[mi][ni][0] + bia0;
            o[1] = acc[mi][ni][1] + bia1;
            o += 8*ldc;
            o[0] = acc[mi][ni][2] + bia0;
            o[1] = acc[mi][ni][3] + bia1;
        }
    }
}

// dispatcher: blocks [0,256) = Gemb GEMM (8 mtiles x 32 ntiles),
//             blocks [256,384) = proj GEMM (16 mtiles x 8 ntiles)
__global__ void __launch_bounds__(256, 2)
k_hmm2(const float* __restrict__ b_ih, const float* __restrict__ b_hh)
{
    extern __shared__ char vsm[];
    const int blk = blockIdx.x;
    if (blk < 256){
        hmm_body(blk & 7, blk >> 3, vsm,
                 g_Eh, g_El, EE, g_gWh, g_gWl, KX,
                 g_Gemb, JG, b_ih, b_hh);
    } else {
        int b2 = blk - 256;
        hmm_body(b2 & 15, b2 >> 4, vsm,
                 g_ENh, g_ENl, HH, g_WAh, g_WAl, HH,
                 g_proj, HH, nullptr, nullptr);
    }
}

// ---------------------------------------------------------------------------
// gates-h-part GEMM, standalone for t=0 prologue (R13-proven)
// ---------------------------------------------------------------------------
#define GSTR 72
#define ABUF 46080

__global__ void __launch_bounds__(256)
k_gh0()
{
    extern __shared__ char dsm[];
    const int tid = threadIdx.x;
    const int ct = blockIdx.x;
    const int nt = ct & 15, z2 = ct >> 4;
    const unsigned base = smem_u32(dsm);
    const int w = tid >> 5, l = tid & 31;
    const int nbase = nt * 128;
    const int n0 = w * 16;
    const int arow  = (l & 7) + ((l >> 3) & 1) * 8;
    const int akoff = (l >> 4) * 8;
    const int brow  = (l & 7) + ((l >> 4) & 1) * 8;
    const int bkoff = ((l >> 3) & 1) * 8;

    auto issue = [&](int buf, int ck){
        const int koff = 1024 + z2*128 + ck*64;
        const unsigned uAh = base + buf*ABUF;
        const unsigned uAl = uAh + 4608;
        const unsigned uBh = uAh + 9216;
        const unsigned uBl = uAh + 27648;
        #pragma unroll
        for (int q = 0; q < 10; q++){
            int i = q*256 + tid;
            if (i < 512){
                int idx = i & 255; int row = idx >> 3, c8 = idx & 7;
                const __nv_bfloat16* src = (i < 256 ? g_Xh : g_Xl)
                                           + (size_t)row*KX + koff + c8*8;
                unsigned dst = (i < 256 ? uAh : uAl) + (unsigned)(row*GSTR + c8*8)*2;
                cpa16(dst, src);
            } else {
                int idx = (i - 512) & 1023; int row = idx >> 3, c8 = idx & 7;
                const __nv_bfloat16* src = (i < 1536 ? g_gWh : g_gWl)
                                           + (size_t)(nbase+row)*KX + koff + c8*8;
                unsigned dst = (i < 1536 ? uBh : uBl) + (unsigned)(row*GSTR + c8*8)*2;
                cpa16(dst, src);
            }
        }
    };

    float acc[2][2][4];
    #pragma unroll
    for (int mi=0;mi<2;mi++)
        #pragma unroll
        for (int ni=0;ni<2;ni++)
            #pragma unroll
            for (int q=0;q<4;q++) acc[mi][ni][q]=0.f;

    issue(0, 0); CP_COMMIT();
    for (int ck = 0; ck < 2; ck++){
        int buf = ck;
        if (ck == 0){ issue(1, 1); CP_COMMIT(); CP_WAIT(1); }
        else        { CP_WAIT(0); }
        __syncthreads();
        const unsigned uAh = base + buf*ABUF;
        const unsigned uAl = uAh + 4608;
        const unsigned uBh = uAh + 9216;
        const unsigned uBl = uAh + 27648;
        #pragma unroll
        for (int ks = 0; ks < 64; ks += 16){
            unsigned afh[2][4], afl[2][4], bfh[4], bfl[4];
            #pragma unroll
            for (int mi=0;mi<2;mi++){
                ldmx4(afh[mi], uAh + (unsigned)((mi*16 + arow)*GSTR + ks + akoff)*2);
                ldmx4(afl[mi], uAl + (unsigned)((mi*16 + arow)*GSTR + ks + akoff)*2);
            }
            ldmx4(bfh, uBh + (unsigned)((n0 + brow)*GSTR + ks + bkoff)*2);
            ldmx4(bfl, uBl + (unsigned)((n0 + brow)*GSTR + ks + bkoff)*2);
            #pragma unroll
            for (int mi=0;mi<2;mi++)
                #pragma unroll
                for (int ni=0;ni<2;ni++){
                    mma16816(acc[mi][ni], afh[mi], bfh[ni*2], bfh[ni*2+1]);
                    mma16816(acc[mi][ni], afh[mi], bfl[ni*2], bfl[ni*2+1]);
                    mma16816(acc[mi][ni], afl[mi], bfh[ni*2], bfh[ni*2+1]);
                }
        }
        __syncthreads();
    }

    #pragma unroll
    for (int mi=0;mi<2;mi++){
        #pragma unroll
        for (int ni=0;ni<2;ni++){
            int row = mi*16 + (l >> 2);
            int col = nbase + n0 + ni*8 + (l & 3)*2;
            float* gp = g_GpartH + ((size_t)z2*BB + row)*JG + col;
            gp[0] = acc[mi][ni][0];
            gp[1] = acc[mi][ni][1];
            gp += 8*JG;
            gp[0] = acc[mi][ni][2];
            gp[1] = acc[mi][ni][3];
        }
    }
}

// ---------------------------------------------------------------------------
// convW slice (in-loop idle CTAs)
// ---------------------------------------------------------------------------
__device__ __forceinline__ void convW_item(const float* __restrict__ W, unsigned i4)
{
    size_t i = (size_t)i4 * 4;
    float4 v = *(const float4*)(W + i);
    __nv_bfloat16 h0, h1, h2, h3, l0, l1, l2, l3;
    bsplit(v.x, h0, l0); bsplit(v.y, h1, l1);
    bsplit(v.z, h2, l2); bsplit(v.w, h3, l3);
    *(__nv_bfloat162*)(g_Wh + i)     = __nv_bfloat162(h0, h1);
    *(__nv_bfloat162*)(g_Wh + i + 2) = __nv_bfloat162(h2, h3);
    *(__nv_bfloat162*)(g_Wl + i)     = __nv_bfloat162(l0, l1);
    *(__nv_bfloat162*)(g_Wl + i + 2) = __nv_bfloat162(l2, l3);
}

// ---------------------------------------------------------------------------
// Persistent recurrent loop (R13-proven structure)
// ---------------------------------------------------------------------------
#define OFF_WHB 36864
#define OFF_XC  36864
#define OFF_SCR 110592

__global__ void __launch_bounds__(256)
k_loop(const int* __restrict__ lens, const float* __restrict__ enc,
       const float* __restrict__ W_c, const float* __restrict__ b_c,
       const float* __restrict__ W_o)
{
    extern __shared__ char dsm[];
    const int ct  = blockIdx.x;
    const int tid = threadIdx.x;
    const int w = tid >> 5, l = tid & 31;
    const unsigned base = smem_u32(dsm);

    const int nt = ct & 15;
    const int z  = ct >> 4;
    const int nbase = nt * 128;
    const int n0 = w * 16;
    const int arow  = (l & 7) + ((l >> 3) & 1) * 8;
    const int akoff = (l >> 4) * 8;
    const int brow  = (l & 7) + ((l >> 4) & 1) * 8;
    const int bkoff = ((l >> 3) & 1) * 8;

    float wreg[32];
    float wbias = 0.f;
    if (ct < 64){
        const int c = ct*8 + w;
        const float* wr = W_c + (size_t)c*1024;
        #pragma unroll
        for (int q=0;q<32;q++) wreg[q] = wr[l + q*32];
        wbias = b_c[c];
    }

    // pre-stage resident weights
    {
        const int koff = 512 + z*64;
        #pragma unroll
        for (int q = 0; q < 8; q++){
            int i = q*256 + tid;
            int idx = i & 1023; int row = idx >> 3, c8 = idx & 7;
            const __nv_bfloat16* src = (i < 1024 ? g_gWh : g_gWl)
                                       + (size_t)(nbase+row)*KX + koff + c8*8;
            unsigned dst = base + (i < 1024 ? 0u : 18432u)
                         + (unsigned)(row*GSTR + c8*8)*2;
            cpa16(dst, src);
        }
        if (ct >= 64){
            const int nt2 = (ct-64) & 15, z2 = (ct-64) >> 4;
            const int nb2 = nt2 * 128;
            #pragma unroll
            for (int ck = 0; ck < 2; ck++){
                const int koff2 = 1024 + z2*128 + ck*64;
                #pragma unroll
                for (int q = 0; q < 8; q++){
                    int i = q*256 + tid;
                    int idx = i & 1023; int row = idx >> 3, c8 = idx & 7;
                    const __nv_bfloat16* src = (i < 1024 ? g_gWh : g_gWl)
                                               + (size_t)(nb2+row)*KX + koff2 + c8*8;
                    unsigned dst = base + OFF_WHB + (unsigned)ck*36864u
                                 + (i < 1024 ? 0u : 18432u)
                                 + (unsigned)(row*GSTR + c8*8)*2;
                    cpa16(dst, src);
                }
            }
        }
        CP_COMMIT(); CP_WAIT(0);
        __syncthreads();
    }

    unsigned nb = 0;

    for (int t = 0; t < T1; t++){
        // ===== Phase A =====
        {
            const unsigned uAh = base + OFF_SCR;
            const unsigned uAl = uAh + 4608;
            const unsigned uBh = base;
            const unsigned uBl = base + 18432;
            const int koff = 512 + z*64;
            #pragma unroll
            for (int q = 0; q < 2; q++){
                int i = q*256 + tid;
                int idx = i & 255; int row = idx >> 3, c8 = idx & 7;
                const __nv_bfloat16* src = (i < 256 ? g_Xh : g_Xl)
                                           + (size_t)row*KX + koff + c8*8;
                unsigned dst = (i < 256 ? uAh : uAl) + (unsigned)(row*GSTR + c8*8)*2;
                cpa16(dst, src);
            }
            CP_COMMIT(); CP_WAIT(0);
            __syncthreads();

            float acc[2][2][4];
            #pragma unroll
            for (int mi=0;mi<2;mi++)
                #pragma unroll
                for (int ni=0;ni<2;ni++)
                    #pragma unroll
                    for (int q=0;q<4;q++) acc[mi][ni][q]=0.f;

            #pragma unroll
            for (int ks = 0; ks < 64; ks += 16){
                unsigned afh[2][4], afl[2][4], bfh[4], bfl[4];
                #pragma unroll
                for (int mi=0;mi<2;mi++){
                    ldmx4(afh[mi], uAh + (unsigned)((mi*16 + arow)*GSTR + ks + akoff)*2);
                    ldmx4(afl[mi], uAl + (unsigned)((mi*16 + arow)*GSTR + ks + akoff)*2);
                }
                ldmx4(bfh, uBh + (unsigned)((n0 + brow)*GSTR + ks + bkoff)*2);
                ldmx4(bfl, uBl + (unsigned)((n0 + brow)*GSTR + ks + bkoff)*2);
                #pragma unroll
                for (int mi=0;mi<2;mi++)
                    #pragma unroll
                    for (int ni=0;ni<2;ni++){
                        mma16816(acc[mi][ni], afh[mi], bfh[ni*2], bfh[ni*2+1]);
                        mma16816(acc[mi][ni], afh[mi], bfl[ni*2], bfl[ni*2+1]);
                        mma16816(acc[mi][ni], afl[mi], bfh[ni*2], bfh[ni*2+1]);
                    }
            }
            __syncthreads();

            #pragma unroll
            for (int mi=0;mi<2;mi++){
                #pragma unroll
                for (int ni=0;ni<2;ni++){
                    int row = mi*16 + (l >> 2);
                    int col = nbase + n0 + ni*8 + (l & 3)*2;
                    float* gp = g_GpartA + ((size_t)z*BB + row)*JG + col;
                    gp[0] = acc[mi][ni][0];
                    gp[1] = acc[mi][ni][1];
                    gp += 8*JG;
                    gp[0] = acc[mi][ni][2];
                    gp[1] = acc[mi][ni][3];
                }
            }
        }
        gbar(++nb * NCTA);

        // ===== Phase B =====
        if (ct < BB){
            const int b = ct;
            float* hh = (float*)(dsm + OFF_SCR);
            float* sc = hh + HH;
            const int len = lens[b];

            #pragma unroll
            for (int rep = 0; rep < 2; rep++){
                int h = tid + rep*256;
                float gv[4];
                #pragma unroll
                for (int q=0;q<4;q++){
                    int j = q*HH + h;
                    float s = g_Gemb[((size_t)t*BB + b)*JG + j];
                    #pragma unroll
                    for (int zz=0;zz<8;zz++) s += g_GpartA[((size_t)zz*BB + b)*JG + j];
                    #pragma unroll
                    for (int zz=0;zz<4;zz++) s += g_GpartH[((size_t)zz*BB + b)*JG + j];
                    gv[q] = s;
                }
                int idx = b*HH + h;
                float ig = sigf(gv[0]);
                float fg = sigf(gv[1]);
                float gg = tanhf(gv[2]);
                float og = sigf(gv[3]);
                float c  = fg * g_c[idx] + ig * gg;
                g_c[idx] = c;
                float h2 = og * tanhf(c);
                g_h[idx] = h2;
                hh[h] = h2;
                g_XC[b*1024 + h] = h2;
                __nv_bfloat16 hi, lo; bsplit(h2, hi, lo);
                g_Xh[b*KX + 1024 + h] = hi;
                g_Xl[b*KX + 1024 + h] = lo;
            }
            __syncthreads();

            #pragma unroll
            for (int i = 0; i < 8; i++){
                int s = w*8 + i;
                const float* pr = &g_proj[((size_t)s*BB + b)*HH];
                float sum = 0.f;
                #pragma unroll
                for (int k = 0; k < 16; k++) sum += hh[l + k*32] * pr[l + k*32];
                #pragma unroll
                for (int off=16; off>0; off>>=1) sum += __shfl_xor_sync(0xffffffffu, sum, off);
                if (l == 0) sc[s] = (s < len) ? sum : -1e9f;
            }
            __syncthreads();

            if (tid < 32){
                float v0 = sc[tid], v1 = sc[tid+32];
                float m = fmaxf(v0, v1);
                #pragma unroll
                for (int off=16; off>0; off>>=1) m = fmaxf(m, __shfl_xor_sync(0xffffffffu, m, off));
                float e0 = expf(v0 - m), e1 = expf(v1 - m);
                float s = e0 + e1;
                #pragma unroll
                for (int off=16; off>0; off>>=1) s += __shfl_xor_sync(0xffffffffu, s, off);
                float inv = 1.0f / s;
                sc[tid]    = e0 * inv;
                sc[tid+32] = e1 * inv;
            }
            __syncthreads();

            #pragma unroll
            for (int rep = 0; rep < 2; rep++){
                int h = tid + rep*256;
                float a0=0.f, a1=0.f, a2=0.f, a3=0.f;
                #pragma unroll 4
                for (int s0 = 0; s0 < 16; s0++){
                    a0 += sc[s0]      * enc[((size_t)(s0)*BB    + b)*HH + h];
                    a1 += sc[s0 + 16] * enc[((size_t)(s0+16)*BB + b)*HH + h];
                    a2 += sc[s0 + 32] * enc[((size_t)(s0+32)*BB + b)*HH + h];
                    a3 += sc[s0 + 48] * enc[((size_t)(s0+48)*BB + b)*HH + h];
                }
                g_XC[b*1024 + 512 + h] = (a0 + a1) + (a2 + a3);
            }
        } else {
            unsigned winbase = (unsigned)t * 147456u;
            #pragma unroll
            for (int j = 0; j < 6; j++){
                unsigned i4 = winbase + (unsigned)j*24576u + (unsigned)(ct-32)*256u + tid;
                if (i4 < WF4) convW_item(W_o, i4);
            }
        }
        gbar(++nb * NCTA);

        // ===== Phase C =====
        if (ct < 64){
            float* xc = (float*)(dsm + OFF_XC);
            const int c = ct*8 + w;
            #pragma unroll
            for (int half = 0; half < 2; half++){
                if (half) __syncthreads();
                {
                    const float4* src = (const float4*)(g_XC + half*16*1024);
                    float4* dst = (float4*)xc;
                    #pragma unroll
                    for (int i = 0; i < 16; i++) dst[tid + i*256] = src[tid + i*256];
                }
                __syncthreads();
                for (int b = 0; b < 16; b++){
                    const float* xb = xc + b*1024;
                    float s = 0.f;
                    #pragma unroll
                    for (int q=0;q<32;q++) s += wreg[q] * xb[l + q*32];
                    #pragma unroll
                    for (int off=16; off>0; off>>=1) s += __shfl_xor_sync(0xffffffffu, s, off);
                    if (l == 0){
                        int gb = half*16 + b;
                        float v = tanhf(s + wbias);
                        __nv_bfloat16 hi, lo; bsplit(v, hi, lo);
                        int r = t*BB + gb;
                        g_Ah[(size_t)r*HH + c] = hi;
                        g_Al[(size_t)r*HH + c] = lo;
                        g_Xh[gb*KX + 512 + c] = hi;
                        g_Xl[gb*KX + 512 + c] = lo;
                    }
                }
            }
        } else if (t + 1 < T1){
            const int z2 = (ct-64) >> 4;
            const int nb2 = ((ct-64) & 15) * 128;
            const unsigned sA = base + OFF_SCR;

            auto issueA = [&](int buf, int ck){
                const int koff = 1024 + z2*128 + ck*64;
                const unsigned uAh = sA + buf*9216;
                const unsigned uAl = uAh + 4608;
                #pragma unroll
                for (int q = 0; q < 2; q++){
                    int i = q*256 + tid;
                    int idx = i & 255; int row = idx >> 3, c8 = idx & 7;
                    const __nv_bfloat16* src = (i < 256 ? g_Xh : g_Xl)
                                               + (size_t)row*KX + koff + c8*8;
                    unsigned dst = (i < 256 ? uAh : uAl) + (unsigned)(row*GSTR + c8*8)*2;
                    cpa16(dst, src);
                }
            };

            float acc[2][2][4];
            #pragma unroll
            for (int mi=0;mi<2;mi++)
                #pragma unroll
                for (int ni=0;ni<2;ni++)
                    #pragma unroll
                    for (int q=0;q<4;q++) acc[mi][ni][q]=0.f;

            issueA(0, 0); CP_COMMIT();
            #pragma unroll
            for (int ck = 0; ck < 2; ck++){
                if (ck == 0){ issueA(1, 1); CP_COMMIT(); CP_WAIT(1); }
                else        { CP_WAIT(0); }
                __syncthreads();
                const unsigned uAh = sA + ck*9216;
                const unsigned uAl = uAh + 4608;
                const unsigned uBh = base + OFF_WHB + ck*36864;
                const unsigned uBl = uBh + 18432;
                #pragma unroll
                for (int ks = 0; ks < 64; ks += 16){
                    unsigned afh[2][4], afl[2][4], bfh[4], bfl[4];
                    #pragma unroll
                    for (int mi=0;mi<2;mi++){
                        ldmx4(afh[mi], uAh + (unsigned)((mi*16 + arow)*GSTR + ks + akoff)*2);
                        ldmx4(afl[mi], uAl + (unsigned)((mi*16 + arow)*GSTR + ks + akoff)*2);
                    }
                    ldmx4(bfh, uBh + (unsigned)((n0 + brow)*GSTR + ks + bkoff)*2);
                    ldmx4(bfl, uBl + (unsigned)((n0 + brow)*GSTR + ks + bkoff)*2);
                    #pragma unroll
                    for (int mi=0;mi<2;mi++)
                        #pragma unroll
                        for (int ni=0;ni<2;ni++){
                            mma16816(acc[mi][ni], afh[mi], bfh[ni*2], bfh[ni*2+1]);
                            mma16816(acc[mi][ni], afh[mi], bfl[ni*2], bfl[ni*2+1]);
                            mma16816(acc[mi][ni], afl[mi], bfh[ni*2], bfh[ni*2+1]);
                        }
                }
                __syncthreads();
            }

            #pragma unroll
            for (int mi=0;mi<2;mi++){
                #pragma unroll
                for (int ni=0;ni<2;ni++){
                    int row = mi*16 + (l >> 2);
                    int col = nb2 + n0 + ni*8 + (l & 3)*2;
                    float* gp = g_GpartH + ((size_t)z2*BB + row)*JG + col;
                    gp[0] = acc[mi][ni][0];
                    gp[1] = acc[mi][ni][1];
                    gp += 8*JG;
                    gp[0] = acc[mi][ni][2];
                    gp[1] = acc[mi][ni][3];
                }
            }
        }
        gbar(++nb * NCTA);
    }
}

// ---------------------------------------------------------------------------
// Vocab GEMM: single K-pass 3-term, software-pipelined fragments (R13-proven)
// ---------------------------------------------------------------------------
__global__ void __launch_bounds__(256, 2)
k_vocab(const float* __restrict__ b_o, float* __restrict__ logits)
{
    extern __shared__ char vsm[];
    const int tid  = threadIdx.x;
    const int wid  = tid >> 5, lane = tid & 31;
    const int mtile = blockIdx.x;
    const int ntile = blockIdx.y;

    const __nv_bfloat16* Asrc_h = g_Ah + (size_t)mtile*128*HH;
    const __nv_bfloat16* Asrc_l = g_Al + (size_t)mtile*128*HH;
    const __nv_bfloat16* Bsrc_h = g_Wh + (size_t)ntile*64*HH;
    const __nv_bfloat16* Bsrc_l = g_Wl + (size_t)ntile*64*HH;

    const unsigned base = smem_u32(vsm);
    const unsigned uAh = base;
    const unsigned uAl = base + 20480;
    const unsigned uBh = base + 40960;
    const unsigned uBl = base + 51200;

    auto issue = [&](int buf, int ch){
        const int k0 = ch*32;
        const unsigned a_h = uAh + buf*10240;
        const unsigned a_l = uAl + buf*10240;
        const unsigned b_h = uBh + buf*5120;
        const unsigned b_l = uBl + buf*5120;
        #pragma unroll
        for (int q = 0; q < 6; q++){
            int i = q*256 + tid;
            if (i < 1024){
                int j = i & 511; int r = j >> 2, c8 = (j & 3)*8;
                const __nv_bfloat16* src = (i < 512 ? Asrc_h : Asrc_l)
                                           + (size_t)r*HH + k0 + c8;
                unsigned dst = (i < 512 ? a_h : a_l) + (unsigned)(r*VK_STR + c8)*2;
                cpa16(dst, src);
            } else {
                int j = (i - 1024) & 255; int r = j >> 2, c8 = (j & 3)*8;
                const __nv_bfloat16* src = (i < 1280 ? Bsrc_h : Bsrc_l)
                                           + (size_t)r*HH + k0 + c8;
                unsigned dst = (i < 1280 ? b_h : b_l) + (unsigned)(r*VK_STR + c8)*2;
                cpa16(dst, src);
            }
        }
    };

    float acc[2][4][4];
    #pragma unroll
    for (int mi=0;mi<2;mi++)
        #pragma unroll
        for (int ni=0;ni<4;ni++)
            #pragma unroll
            for (int q=0;q<4;q++) acc[mi][ni][q]=0.f;

    const int m0 = (wid & 3) * 32;
    const int n0 = (wid >> 2) * 32;
    const int arow  = (lane & 7) + ((lane >> 3) & 1) * 8;
    const int akoff = (lane >> 4) * 8;
    const int brow  = (lane & 7) + ((lane >> 4) & 1) * 8;
    const int bkoff = ((lane >> 3) & 1) * 8;

    issue(0, 0); CP_COMMIT();
    const int NCH = 16;
    for (int ch = 0; ch < NCH; ch++){
        int buf = ch & 1;
        if (ch + 1 < NCH){ issue(buf ^ 1, ch + 1); CP_COMMIT(); CP_WAIT(1); }
        else             { CP_WAIT(0); }
        __syncthreads();
        const unsigned a_h = uAh + buf*10240;
        const unsigned a_l = uAl + buf*10240;
        const unsigned b_h = uBh + buf*5120;
        const unsigned b_l = uBl + buf*5120;

        unsigned afh[2][2][4], afl[2][2][4], bfh[2][2][4], bfl[2][2][4];
        #pragma unroll
        for (int s2 = 0; s2 < 2; s2++){
            const int ks = s2*16;
            #pragma unroll
            for (int mi=0;mi<2;mi++){
                ldmx4(afh[s2][mi], a_h + (unsigned)((m0 + mi*16 + arow)*VK_STR + ks + akoff)*2);
                ldmx4(afl[s2][mi], a_l + (unsigned)((m0 + mi*16 + arow)*VK_STR + ks + akoff)*2);
            }
            #pragma unroll
            for (int g=0; g<2; g++){
                ldmx4(bfh[s2][g], b_h + (unsigned)((n0 + g*16 + brow)*VK_STR + ks + bkoff)*2);
                ldmx4(bfl[s2][g], b_l + (unsigned)((n0 + g*16 + brow)*VK_STR + ks + bkoff)*2);
            }
        }
        #pragma unroll
        for (int s2 = 0; s2 < 2; s2++)
            #pragma unroll
            for (int mi=0;mi<2;mi++)
                #pragma unroll
                for (int ni=0;ni<4;ni++){
                    unsigned h0 = bfh[s2][ni>>1][(ni&1)*2], h1 = bfh[s2][ni>>1][(ni&1)*2+1];
                    unsigned l0 = bfl[s2][ni>>1][(ni&1)*2], l1 = bfl[s2][ni>>1][(ni&1)*2+1];
                    mma16816(acc[mi][ni], afh[s2][mi], h0, h1);
                    mma16816(acc[mi][ni], afh[s2][mi], l0, l1);
                    mma16816(acc[mi][ni], afl[s2][mi], h0, h1);
                }
        __syncthreads();
    }

    #pragma unroll
    for (int mi=0;mi<2;mi++){
        #pragma unroll
        for (int ni=0;ni<4;ni++){
            int row = mtile*128 + m0 + mi*16 + (lane >> 2);
            int col = ntile*64  + n0 + ni*8  + (lane & 3)*2;
            float bia0 = b_o[col], bia1 = b_o[col+1];
            if (row < T1*BB){
                float* o = logits + (size_t)row*VV + col;
                o[0] = acc[mi][ni][0] + bia0;
                o[1] = acc[mi][ni][1] + bia1;
            }
            if (row + 8 < T1*BB){
                float* o = logits + (size_t)(row+8)*VV + col;
                o[0] = acc[mi][ni][2] + bia0;
                o[1] = acc[mi][ni][3] + bia1;
            }
        }
    }
}

// ---------------------------------------------------------------------------
// Online log-softmax + argmax : 512 threads, float4 (R13-proven)
// ---------------------------------------------------------------------------
__global__ void __launch_bounds__(512)
k_lsm(float* __restrict__ logits)
{
    __shared__ float ms[512], ss[512];
    __shared__ int   ii[512];
    const int row = blockIdx.x;
    const int tid = threadIdx.x;
    float* x = logits + (size_t)row * VV;
    const float4* x4 = (const float4*)x;
    const int N4 = VV/4;

    float4 v0 = x4[tid];
    float m = v0.x; int mi = tid*4; float s = 1.f;
    {
        float vals[3] = {v0.y, v0.z, v0.w};
        #pragma unroll
        for (int j=0;j<3;j++){
            float v = vals[j];
            if (v > m){ s = s*fexp(m - v) + 1.f; m = v; mi = tid*4 + j + 1; }
            else        s += fexp(v - m);
        }
    }
    for (int i4 = tid + 512; i4 < N4; i4 += 512){
        float4 v4 = x4[i4];
        float vals[4] = {v4.x, v4.y, v4.z, v4.w};
        #pragma unroll
        for (int j=0;j<4;j++){
            float v = vals[j];
            if (v > m){ s = s*fexp(m - v) + 1.f; m = v; mi = i4*4 + j; }
            else        s += fexp(v - m);
        }
    }
    ms[tid]=m; ss[tid]=s; ii[tid]=mi;
    __syncthreads();
    for (int st = 256; st > 0; st >>= 1){
        if (tid < st){
            float m1=ms[tid], s1=ss[tid]; int i1=ii[tid];
            float m2=ms[tid+st], s2=ss[tid+st]; int i2=ii[tid+st];
            if (m2 > m1)      { ms[tid]=m2; ss[tid]=s1*fexp(m1-m2)+s2; ii[tid]=i2; }
            else if (m2 < m1) { ss[tid]=s1+s2*fexp(m2-m1); }
            else              { ss[tid]=s1+s2; ii[tid]=min(i1,i2); }
        }
        __syncthreads();
    }
    float lse = ms[0] + logf(ss[0]);
    if (tid == 0) g_argmax[row] = ii[0];

    float4* xw = (float4*)x;
    for (int i4 = tid; i4 < N4; i4 += 512){
        float4 v4 = xw[i4];
        v4.x -= lse; v4.y -= lse; v4.z -= lse; v4.w -= lse;
        xw[i4] = v4;
    }
}

__global__ void k_tail_f(float* __restrict__ out)
{
    int r = blockIdx.x*blockDim.x + threadIdx.x;
    if (r < T1*BB) out[TBV + r] = (float)g_argmax[r];
}
__global__ void k_tail_i(int* __restrict__ out)
{
    int r = blockIdx.x*blockDim.x + threadIdx.x;
    if (r < T1*BB) out[r] = g_argmax[r];
}

// ---------------------------------------------------------------------------
extern "C" void kernel_launch(void* const* d_in, const int* in_sizes, int n_in,
                              void* d_out, int out_size)
{
    const int*   tgt   = (const int*)  d_in[0];
    const int*   lens  = (const int*)  d_in[1];
    const float* enc   = (const float*)d_in[2];
    const float* h0    = (const float*)d_in[3];
    const float* c0    = (const float*)d_in[4];
    const float* emb   = (const float*)d_in[5];
    const float* W_ih  = (const float*)d_in[6];
    const float* W_hh  = (const float*)d_in[7];
    const float* b_ih  = (const float*)d_in[8];
    const float* b_hh  = (const float*)d_in[9];
    const float* W_a   = (const float*)d_in[10];
    const float* W_c   = (const float*)d_in[11];
    const float* b_c   = (const float*)d_in[12];
    const float* W_o   = (const float*)d_in[13];
    const float* b_o   = (const float*)d_in[14];

    float *p_lg = nullptr;
    cudaGetSymbolAddress((void**)&p_lg, g_logits);

    const bool big = (size_t)out_size >= TBV;
    float* logits = big ? (float*)d_out : p_lg;

    cudaFuncSetAttribute(k_loop,   cudaFuncAttributeMaxDynamicSharedMemorySize, 131072);
    cudaFuncSetAttribute(k_gh0,    cudaFuncAttributeMaxDynamicSharedMemorySize, 2*ABUF);
    cudaFuncSetAttribute(k_vocab,  cudaFuncAttributeMaxDynamicSharedMemorySize, 61440);
    cudaFuncSetAttribute(k_hmm2,   cudaFuncAttributeMaxDynamicSharedMemorySize, 61440);

    // prologue: conversions + prep (one launch), then both HMMA GEMMs (one launch)
    k_convall<<<4928, 256>>>(tgt, emb, W_ih, W_hh, enc, W_a, h0, c0);
    k_hmm2<<<384, 256, 61440>>>(b_ih, b_hh);
    k_gh0<<<64, 256, 2*ABUF>>>();

    // persistent recurrent loop (R13-proven)
    k_loop<<<NCTA, 256, 131072>>>(lens, enc, W_c, b_c, W_o);

    // vocab projection + log-softmax
    k_vocab<<<dim3(8, 500), 256, 61440>>>(b_o, logits);
    k_lsm<<<T1*BB, 512>>>(logits);

    if (big && (size_t)out_size >= TBV + (size_t)T1*BB) {
        k_tail_f<<<4, 256>>>((float*)d_out);
    } else if (!big) {
        k_tail_i<<<4, 256>>>((int*)d_out);
    }
}

// round 16
// speedup vs baseline: 1.5806x; 1.1940x over previous
#include <cuda_runtime.h>
#include <cuda_bf16.h>
#include <math.h>

// Problem constants
#define BB 32
#define TT 32
#define SS 64
#define HH 512
#define EE 512
#define VV 32000
#define T1 (TT-1)
#define TBV ((size_t)T1*BB*VV)
#define BH (BB*HH)
#define MPAD 1024
#define KX 1536
#define JG 2048
#define NCTA 128
#define WF4 4096000u    // VV*HH/4

// -------- persistent device scratch --------
__device__ float g_h[BH];
__device__ float g_c[BH];
__device__ __align__(16) float g_proj[2048*HH];
__device__ __align__(16) float g_XC[BB*1024];
__device__ __align__(16) float g_GpartA[8*BB*JG];
__device__ __align__(16) float g_GpartH[4*BB*JG];
__device__ __align__(16) float g_Gemb[MPAD*JG];
__device__ int   g_argmax[T1*BB];
__device__ float g_logits[T1*BB*VV];
__device__ __align__(16) __nv_bfloat16 g_Wh[(size_t)VV*HH];
__device__ __align__(16) __nv_bfloat16 g_Wl[(size_t)VV*HH];
__device__ __align__(16) __nv_bfloat16 g_Ah[MPAD*HH];   // rows 992..1023 stay 0
__device__ __align__(16) __nv_bfloat16 g_Al[MPAD*HH];
__device__ __align__(16) __nv_bfloat16 g_gWh[JG*KX];
__device__ __align__(16) __nv_bfloat16 g_gWl[JG*KX];
__device__ __align__(16) __nv_bfloat16 g_Xh[BB*KX];
__device__ __align__(16) __nv_bfloat16 g_Xl[BB*KX];
__device__ __align__(16) __nv_bfloat16 g_Eh[MPAD*EE];
__device__ __align__(16) __nv_bfloat16 g_El[MPAD*EE];
__device__ __align__(16) __nv_bfloat16 g_ENh[2048*HH];
__device__ __align__(16) __nv_bfloat16 g_ENl[2048*HH];
__device__ __align__(16) __nv_bfloat16 g_WAh[HH*HH];
__device__ __align__(16) __nv_bfloat16 g_WAl[HH*HH];
__device__ unsigned g_barcnt;

__device__ __forceinline__ float sigf(float x){ return 1.0f/(1.0f+expf(-x)); }

__device__ __forceinline__ float fexp(float x){
    float t = x * 1.4426950408889634f;
    float n = rintf(t);
    float f = t - n;
    float p = 1.5403530e-4f;
    p = fmaf(p, f, 1.3333558e-3f);
    p = fmaf(p, f, 9.6181291e-3f);
    p = fmaf(p, f, 5.5504109e-2f);
    p = fmaf(p, f, 2.4022651e-1f);
    p = fmaf(p, f, 6.9314718e-1f);
    p = fmaf(p, f, 1.0f);
    int e = (int)n;
    e = e < -126 ? -126 : (e > 127 ? 127 : e);
    float sc = __int_as_float((e+127)<<23);
    return p*sc;
}

// ------------------ low-level helpers ------------------
__device__ __forceinline__ unsigned smem_u32(const void* p){
    unsigned a;
    asm("{ .reg .u64 t; cvta.to.shared.u64 t, %1; cvt.u32.u64 %0, t; }" : "=r"(a) : "l"(p));
    return a;
}
__device__ __forceinline__ void cpa16(unsigned dst, const void* src){
    asm volatile("cp.async.cg.shared.global [%0], [%1], 16;" :: "r"(dst), "l"(src));
}
#define CP_COMMIT() asm volatile("cp.async.commit_group;" ::: "memory")
#define CP_WAIT(n)  asm volatile("cp.async.wait_group %0;" :: "n"(n) : "memory")

__device__ __forceinline__ void ldmx4(unsigned* r, unsigned addr){
    asm volatile("ldmatrix.sync.aligned.m8n8.x4.shared.b16 {%0,%1,%2,%3}, [%4];"
        : "=r"(r[0]), "=r"(r[1]), "=r"(r[2]), "=r"(r[3]) : "r"(addr));
}
__device__ __forceinline__ void mma16816(float* d, const unsigned* a,
                                         unsigned b0, unsigned b1){
    asm volatile(
        "mma.sync.aligned.m16n8k16.row.col.f32.bf16.bf16.f32 "
        "{%0,%1,%2,%3}, {%4,%5,%6,%7}, {%8,%9}, {%0,%1,%2,%3};"
        : "+f"(d[0]), "+f"(d[1]), "+f"(d[2]), "+f"(d[3])
        : "r"(a[0]), "r"(a[1]), "r"(a[2]), "r"(a[3]), "r"(b0), "r"(b1));
}
__device__ __forceinline__ void bsplit(float v, __nv_bfloat16& hi, __nv_bfloat16& lo){
    hi = __float2bfloat16(v);
    lo = __float2bfloat16(v - __bfloat162float(hi));
}

// PROVEN R10 spin grid barrier: sc-fence + atomicAdd arrive, acquire poll.
__device__ __forceinline__ void gbar(unsigned target){
    __syncthreads();
    if (threadIdx.x == 0){
        __threadfence();
        atomicAdd(&g_barcnt, 1u);
        unsigned v;
        do {
            asm volatile("ld.global.acquire.gpu.b32 %0, [%1];"
                         : "=r"(v) : "l"(&g_barcnt));
        } while (v < target);
    }
    __syncthreads();
}

// ---------------------------------------------------------------------------
// Merged conversion prologue + prep0 (R15-proven)
// ---------------------------------------------------------------------------
__global__ void k_convall(const int* __restrict__ tgt, const float* __restrict__ emb,
                          const float* __restrict__ W_ih, const float* __restrict__ W_hh,
                          const float* __restrict__ enc, const float* __restrict__ W_a,
                          const float* __restrict__ h0, const float* __restrict__ c0)
{
    const int blk = blockIdx.x;
    if (blk < 512){
        int i = (blk*256 + threadIdx.x)*4;
        int r = i >> 9, k = i & 511;
        float4 v = make_float4(0.f,0.f,0.f,0.f);
        if (r < T1*BB){
            int t = r >> 5, b = r & 31;
            int w = tgt[b*TT + t];
            v = *(const float4*)(emb + (size_t)w*EE + k);
        }
        __nv_bfloat16 h0b,h1,h2,h3,l0,l1,l2,l3;
        bsplit(v.x,h0b,l0); bsplit(v.y,h1,l1); bsplit(v.z,h2,l2); bsplit(v.w,h3,l3);
        *(__nv_bfloat162*)(g_Eh + i)     = __nv_bfloat162(h0b,h1);
        *(__nv_bfloat162*)(g_Eh + i + 2) = __nv_bfloat162(h2,h3);
        *(__nv_bfloat162*)(g_El + i)     = __nv_bfloat162(l0,l1);
        *(__nv_bfloat162*)(g_El + i + 2) = __nv_bfloat162(l2,l3);
    } else if (blk < 3584){
        size_t i = ((size_t)(blk-512)*256 + threadIdx.x)*4;
        if (i >= (size_t)JG*KX) return;
        int j = (int)(i / KX);
        int k = (int)(i % KX);
        float4 v = (k < 1024) ? *(const float4*)(W_ih + (size_t)j*1024 + k)
                              : *(const float4*)(W_hh + (size_t)j*512 + (k-1024));
        __nv_bfloat16 h, l;
        bsplit(v.x, h, l); g_gWh[i+0]=h; g_gWl[i+0]=l;
        bsplit(v.y, h, l); g_gWh[i+1]=h; g_gWl[i+1]=l;
        bsplit(v.z, h, l); g_gWh[i+2]=h; g_gWl[i+2]=l;
        bsplit(v.w, h, l); g_gWh[i+3]=h; g_gWl[i+3]=l;
    } else if (blk < 4864){
        size_t i = ((size_t)(blk-3584)*256 + threadIdx.x)*4;
        const size_t NE = (size_t)2048*HH;
        if (i >= NE + (size_t)HH*HH) return;
        const float* src; __nv_bfloat16 *dh, *dl; size_t off;
        if (i < NE){ src = enc;  dh = g_ENh; dl = g_ENl; off = i; }
        else       { src = W_a;  dh = g_WAh; dl = g_WAl; off = i - NE; }
        float4 v = *(const float4*)(src + off);
        __nv_bfloat16 h0b,h1,h2,h3,l0,l1,l2,l3;
        bsplit(v.x,h0b,l0); bsplit(v.y,h1,l1); bsplit(v.z,h2,l2); bsplit(v.w,h3,l3);
        *(__nv_bfloat162*)(dh + off)     = __nv_bfloat162(h0b,h1);
        *(__nv_bfloat162*)(dh + off + 2) = __nv_bfloat162(h2,h3);
        *(__nv_bfloat162*)(dl + off)     = __nv_bfloat162(l0,l1);
        *(__nv_bfloat162*)(dl + off + 2) = __nv_bfloat162(l2,l3);
    } else {
        if (blk == 4864 && threadIdx.x == 0) g_barcnt = 0;
        int idx = (blk-4864)*256 + threadIdx.x;
        int b = idx >> 9, k = idx & 511;
        g_h[idx] = h0[idx];
        g_c[idx] = c0[idx];
        __nv_bfloat16 hi, lo;
        g_Xh[b*KX + 512 + k] = __float2bfloat16(0.f);
        g_Xl[b*KX + 512 + k] = __float2bfloat16(0.f);
        bsplit(h0[idx], hi, lo);
        g_Xh[b*KX + 1024 + k] = hi;  g_Xl[b*KX + 1024 + k] = lo;
    }
}

// ---------------------------------------------------------------------------
// HMMA GEMM body + dispatcher (R15-proven)
// ---------------------------------------------------------------------------
#define VK_STR 40

__device__ __forceinline__ void hmm_body(
    int mtile, int ntile, char* vsm,
    const __nv_bfloat16* __restrict__ Ah, const __nv_bfloat16* __restrict__ Al, int lda,
    const __nv_bfloat16* __restrict__ Bh, const __nv_bfloat16* __restrict__ Bl, int ldb,
    float* __restrict__ C, int ldc,
    const float* __restrict__ bias1, const float* __restrict__ bias2)
{
    const int tid  = threadIdx.x;
    const int wid  = tid >> 5, lane = tid & 31;

    const __nv_bfloat16* Asrc_h = Ah + (size_t)mtile*128*lda;
    const __nv_bfloat16* Asrc_l = Al + (size_t)mtile*128*lda;
    const __nv_bfloat16* Bsrc_h = Bh + (size_t)ntile*64*ldb;
    const __nv_bfloat16* Bsrc_l = Bl + (size_t)ntile*64*ldb;

    const unsigned base = smem_u32(vsm);
    const unsigned uAh = base;
    const unsigned uAl = base + 20480;
    const unsigned uBh = base + 40960;
    const unsigned uBl = base + 51200;

    auto issue = [&](int buf, int ch){
        const int k0 = ch*32;
        const unsigned a_h = uAh + buf*10240;
        const unsigned a_l = uAl + buf*10240;
        const unsigned b_h = uBh + buf*5120;
        const unsigned b_l = uBl + buf*5120;
        #pragma unroll
        for (int q = 0; q < 6; q++){
            int i = q*256 + tid;
            if (i < 1024){
                int j = i & 511; int r = j >> 2, c8 = (j & 3)*8;
                const __nv_bfloat16* src = (i < 512 ? Asrc_h : Asrc_l)
                                           + (size_t)r*lda + k0 + c8;
                unsigned dst = (i < 512 ? a_h : a_l) + (unsigned)(r*VK_STR + c8)*2;
                cpa16(dst, src);
            } else {
                int j = (i - 1024) & 255; int r = j >> 2, c8 = (j & 3)*8;
                const __nv_bfloat16* src = (i < 1280 ? Bsrc_h : Bsrc_l)
                                           + (size_t)r*ldb + k0 + c8;
                unsigned dst = (i < 1280 ? b_h : b_l) + (unsigned)(r*VK_STR + c8)*2;
                cpa16(dst, src);
            }
        }
    };

    float acc[2][4][4];
    #pragma unroll
    for (int mi=0;mi<2;mi++)
        #pragma unroll
        for (int ni=0;ni<4;ni++)
            #pragma unroll
            for (int q=0;q<4;q++) acc[mi][ni][q]=0.f;

    const int m0 = (wid & 3) * 32;
    const int n0 = (wid >> 2) * 32;
    const int arow  = (lane & 7) + ((lane >> 3) & 1) * 8;
    const int akoff = (lane >> 4) * 8;
    const int brow  = (lane & 7) + ((lane >> 4) & 1) * 8;
    const int bkoff = ((lane >> 3) & 1) * 8;

    issue(0, 0); CP_COMMIT();
    const int NCH = 16;
    for (int ch = 0; ch < NCH; ch++){
        int buf = ch & 1;
        if (ch + 1 < NCH){ issue(buf ^ 1, ch + 1); CP_COMMIT(); CP_WAIT(1); }
        else             { CP_WAIT(0); }
        __syncthreads();
        const unsigned a_h = uAh + buf*10240;
        const unsigned a_l = uAl + buf*10240;
        const unsigned b_h = uBh + buf*5120;
        const unsigned b_l = uBl + buf*5120;
        #pragma unroll
        for (int ks = 0; ks < 32; ks += 16){
            unsigned afh[2][4], afl[2][4], bfh[2][4], bfl[2][4];
            #pragma unroll
            for (int mi=0;mi<2;mi++){
                ldmx4(afh[mi], a_h + (unsigned)((m0 + mi*16 + arow)*VK_STR + ks + akoff)*2);
                ldmx4(afl[mi], a_l + (unsigned)((m0 + mi*16 + arow)*VK_STR + ks + akoff)*2);
            }
            #pragma unroll
            for (int g=0; g<2; g++){
                ldmx4(bfh[g], b_h + (unsigned)((n0 + g*16 + brow)*VK_STR + ks + bkoff)*2);
                ldmx4(bfl[g], b_l + (unsigned)((n0 + g*16 + brow)*VK_STR + ks + bkoff)*2);
            }
            #pragma unroll
            for (int mi=0;mi<2;mi++)
                #pragma unroll
                for (int ni=0;ni<4;ni++){
                    unsigned h0 = bfh[ni>>1][(ni&1)*2], h1 = bfh[ni>>1][(ni&1)*2+1];
                    unsigned l0 = bfl[ni>>1][(ni&1)*2], l1 = bfl[ni>>1][(ni&1)*2+1];
                    mma16816(acc[mi][ni], afh[mi], h0, h1);
                    mma16816(acc[mi][ni], afh[mi], l0, l1);
                    mma16816(acc[mi][ni], afl[mi], h0, h1);
                }
        }
        __syncthreads();
    }

    #pragma unroll
    for (int mi=0;mi<2;mi++){
        #pragma unroll
        for (int ni=0;ni<4;ni++){
            int row = mtile*128 + m0 + mi*16 + (lane >> 2);
            int col = ntile*64  + n0 + ni*8  + (lane & 3)*2;
            float bia0 = 0.f, bia1 = 0.f;
            if (bias1){ bia0 += bias1[col]; bia1 += bias1[col+1]; }
            if (bias2){ bia0 += bias2[col]; bia1 += bias2[col+1]; }
            float* o = C + (size_t)row*ldc + col;
            o[0] = acc[mi][ni][0] + bia0;
            o[1] = acc[mi][ni][1] + bia1;
            o += 8*ldc;
            o[0] = acc[mi][ni][2] + bia0;
            o[1] = acc[mi][ni][3] + bia1;
        }
    }
}

__global__ void __launch_bounds__(256, 2)
k_hmm2(const float* __restrict__ b_ih, const float* __restrict__ b_hh)
{
    extern __shared__ char vsm[];
    const int blk = blockIdx.x;
    if (blk < 256){
        hmm_body(blk & 7, blk >> 3, vsm,
                 g_Eh, g_El, EE, g_gWh, g_gWl, KX,
                 g_Gemb, JG, b_ih, b_hh);
    } else {
        int b2 = blk - 256;
        hmm_body(b2 & 15, b2 >> 4, vsm,
                 g_ENh, g_ENl, HH, g_WAh, g_WAl, HH,
                 g_proj, HH, nullptr, nullptr);
    }
}

// ---------------------------------------------------------------------------
// gates-h-part GEMM, standalone for t=0 prologue (R13-proven)
// ---------------------------------------------------------------------------
#define GSTR 72
#define ABUF 46080

__global__ void __launch_bounds__(256)
k_gh0()
{
    extern __shared__ char dsm[];
    const int tid = threadIdx.x;
    const int ct = blockIdx.x;
    const int nt = ct & 15, z2 = ct >> 4;
    const unsigned base = smem_u32(dsm);
    const int w = tid >> 5, l = tid & 31;
    const int nbase = nt * 128;
    const int n0 = w * 16;
    const int arow  = (l & 7) + ((l >> 3) & 1) * 8;
    const int akoff = (l >> 4) * 8;
    const int brow  = (l & 7) + ((l >> 4) & 1) * 8;
    const int bkoff = ((l >> 3) & 1) * 8;

    auto issue = [&](int buf, int ck){
        const int koff = 1024 + z2*128 + ck*64;
        const unsigned uAh = base + buf*ABUF;
        const unsigned uAl = uAh + 4608;
        const unsigned uBh = uAh + 9216;
        const unsigned uBl = uAh + 27648;
        #pragma unroll
        for (int q = 0; q < 10; q++){
            int i = q*256 + tid;
            if (i < 512){
                int idx = i & 255; int row = idx >> 3, c8 = idx & 7;
                const __nv_bfloat16* src = (i < 256 ? g_Xh : g_Xl)
                                           + (size_t)row*KX + koff + c8*8;
                unsigned dst = (i < 256 ? uAh : uAl) + (unsigned)(row*GSTR + c8*8)*2;
                cpa16(dst, src);
            } else {
                int idx = (i - 512) & 1023; int row = idx >> 3, c8 = idx & 7;
                const __nv_bfloat16* src = (i < 1536 ? g_gWh : g_gWl)
                                           + (size_t)(nbase+row)*KX + koff + c8*8;
                unsigned dst = (i < 1536 ? uBh : uBl) + (unsigned)(row*GSTR + c8*8)*2;
                cpa16(dst, src);
            }
        }
    };

    float acc[2][2][4];
    #pragma unroll
    for (int mi=0;mi<2;mi++)
        #pragma unroll
        for (int ni=0;ni<2;ni++)
            #pragma unroll
            for (int q=0;q<4;q++) acc[mi][ni][q]=0.f;

    issue(0, 0); CP_COMMIT();
    for (int ck = 0; ck < 2; ck++){
        int buf = ck;
        if (ck == 0){ issue(1, 1); CP_COMMIT(); CP_WAIT(1); }
        else        { CP_WAIT(0); }
        __syncthreads();
        const unsigned uAh = base + buf*ABUF;
        const unsigned uAl = uAh + 4608;
        const unsigned uBh = uAh + 9216;
        const unsigned uBl = uAh + 27648;
        #pragma unroll
        for (int ks = 0; ks < 64; ks += 16){
            unsigned afh[2][4], afl[2][4], bfh[4], bfl[4];
            #pragma unroll
            for (int mi=0;mi<2;mi++){
                ldmx4(afh[mi], uAh + (unsigned)((mi*16 + arow)*GSTR + ks + akoff)*2);
                ldmx4(afl[mi], uAl + (unsigned)((mi*16 + arow)*GSTR + ks + akoff)*2);
            }
            ldmx4(bfh, uBh + (unsigned)((n0 + brow)*GSTR + ks + bkoff)*2);
            ldmx4(bfl, uBl + (unsigned)((n0 + brow)*GSTR + ks + bkoff)*2);
            #pragma unroll
            for (int mi=0;mi<2;mi++)
                #pragma unroll
                for (int ni=0;ni<2;ni++){
                    mma16816(acc[mi][ni], afh[mi], bfh[ni*2], bfh[ni*2+1]);
                    mma16816(acc[mi][ni], afh[mi], bfl[ni*2], bfl[ni*2+1]);
                    mma16816(acc[mi][ni], afl[mi], bfh[ni*2], bfh[ni*2+1]);
                }
        }
        __syncthreads();
    }

    #pragma unroll
    for (int mi=0;mi<2;mi++){
        #pragma unroll
        for (int ni=0;ni<2;ni++){
            int row = mi*16 + (l >> 2);
            int col = nbase + n0 + ni*8 + (l & 3)*2;
            float* gp = g_GpartH + ((size_t)z2*BB + row)*JG + col;
            gp[0] = acc[mi][ni][0];
            gp[1] = acc[mi][ni][1];
            gp += 8*JG;
            gp[0] = acc[mi][ni][2];
            gp[1] = acc[mi][ni][3];
        }
    }
}

// ---------------------------------------------------------------------------
// convW slice (in-loop idle CTAs)
// ---------------------------------------------------------------------------
__device__ __forceinline__ void convW_item(const float* __restrict__ W, unsigned i4)
{
    size_t i = (size_t)i4 * 4;
    float4 v = *(const float4*)(W + i);
    __nv_bfloat16 h0, h1, h2, h3, l0, l1, l2, l3;
    bsplit(v.x, h0, l0); bsplit(v.y, h1, l1);
    bsplit(v.z, h2, l2); bsplit(v.w, h3, l3);
    *(__nv_bfloat162*)(g_Wh + i)     = __nv_bfloat162(h0, h1);
    *(__nv_bfloat162*)(g_Wh + i + 2) = __nv_bfloat162(h2, h3);
    *(__nv_bfloat162*)(g_Wl + i)     = __nv_bfloat162(l0, l1);
    *(__nv_bfloat162*)(g_Wl + i + 2) = __nv_bfloat162(l2, l3);
}

// ---------------------------------------------------------------------------
// Persistent recurrent loop (R13 structure; phases B/C vectorized)
// smem: [0,36864) phase-A weights | [36864,110592) gatesH weights / XC stage
//       [110592,131072) scratch: A-tiles | phase-B sg(8K)+hh(2K)+sc
// ---------------------------------------------------------------------------
#define OFF_WHB 36864
#define OFF_XC  36864
#define OFF_SCR 110592

__global__ void __launch_bounds__(256)
k_loop(const int* __restrict__ lens, const float* __restrict__ enc,
       const float* __restrict__ W_c, const float* __restrict__ b_c,
       const float* __restrict__ W_o)
{
    extern __shared__ char dsm[];
    const int ct  = blockIdx.x;
    const int tid = threadIdx.x;
    const int w = tid >> 5, l = tid & 31;
    const unsigned base = smem_u32(dsm);

    const int nt = ct & 15;
    const int z  = ct >> 4;
    const int nbase = nt * 128;
    const int n0 = w * 16;
    const int arow  = (l & 7) + ((l >> 3) & 1) * 8;
    const int akoff = (l >> 4) * 8;
    const int brow  = (l & 7) + ((l >> 4) & 1) * 8;
    const int bkoff = ((l >> 3) & 1) * 8;

    // phase-C ah2 assignment: 64 CTAs = 32 colgroups x 2 b-halves; 2 cols/warp
    const int colg = ct & 31;
    const int bh   = ct >> 5;          // valid for ct<64
    const int c0   = colg*16 + w*2;
    float wreg0[32], wreg1[32];
    float wb0 = 0.f, wb1 = 0.f;
    if (ct < 64){
        const float* wr0 = W_c + (size_t)c0*1024;
        const float* wr1 = W_c + (size_t)(c0+1)*1024;
        #pragma unroll
        for (int q=0;q<32;q++){ wreg0[q] = wr0[l + q*32]; wreg1[q] = wr1[l + q*32]; }
        wb0 = b_c[c0]; wb1 = b_c[c0+1];
    }

    // pre-stage resident weights (R13-proven)
    {
        const int koff = 512 + z*64;
        #pragma unroll
        for (int q = 0; q < 8; q++){
            int i = q*256 + tid;
            int idx = i & 1023; int row = idx >> 3, c8 = idx & 7;
            const __nv_bfloat16* src = (i < 1024 ? g_gWh : g_gWl)
                                       + (size_t)(nbase+row)*KX + koff + c8*8;
            unsigned dst = base + (i < 1024 ? 0u : 18432u)
                         + (unsigned)(row*GSTR + c8*8)*2;
            cpa16(dst, src);
        }
        if (ct >= 64){
            const int nt2 = (ct-64) & 15, z2 = (ct-64) >> 4;
            const int nb2 = nt2 * 128;
            #pragma unroll
            for (int ck = 0; ck < 2; ck++){
                const int koff2 = 1024 + z2*128 + ck*64;
                #pragma unroll
                for (int q = 0; q < 8; q++){
                    int i = q*256 + tid;
                    int idx = i & 1023; int row = idx >> 3, c8 = idx & 7;
                    const __nv_bfloat16* src = (i < 1024 ? g_gWh : g_gWl)
                                               + (size_t)(nb2+row)*KX + koff2 + c8*8;
                    unsigned dst = base + OFF_WHB + (unsigned)ck*36864u
                                 + (i < 1024 ? 0u : 18432u)
                                 + (unsigned)(row*GSTR + c8*8)*2;
                    cpa16(dst, src);
                }
            }
        }
        CP_COMMIT(); CP_WAIT(0);
        __syncthreads();
    }

    unsigned nb = 0;

    for (int t = 0; t < T1; t++){
        // ===== Phase A (R13-proven: gates ah-part, resident weights) =====
        {
            const unsigned uAh = base + OFF_SCR;
            const unsigned uAl = uAh + 4608;
            const unsigned uBh = base;
            const unsigned uBl = base + 18432;
            const int koff = 512 + z*64;
            #pragma unroll
            for (int q = 0; q < 2; q++){
                int i = q*256 + tid;
                int idx = i & 255; int row = idx >> 3, c8 = idx & 7;
                const __nv_bfloat16* src = (i < 256 ? g_Xh : g_Xl)
                                           + (size_t)row*KX + koff + c8*8;
                unsigned dst = (i < 256 ? uAh : uAl) + (unsigned)(row*GSTR + c8*8)*2;
                cpa16(dst, src);
            }
            CP_COMMIT(); CP_WAIT(0);
            __syncthreads();

            float acc[2][2][4];
            #pragma unroll
            for (int mi=0;mi<2;mi++)
                #pragma unroll
                for (int ni=0;ni<2;ni++)
                    #pragma unroll
                    for (int q=0;q<4;q++) acc[mi][ni][q]=0.f;

            #pragma unroll
            for (int ks = 0; ks < 64; ks += 16){
                unsigned afh[2][4], afl[2][4], bfh[4], bfl[4];
                #pragma unroll
                for (int mi=0;mi<2;mi++){
                    ldmx4(afh[mi], uAh + (unsigned)((mi*16 + arow)*GSTR + ks + akoff)*2);
                    ldmx4(afl[mi], uAl + (unsigned)((mi*16 + arow)*GSTR + ks + akoff)*2);
                }
                ldmx4(bfh, uBh + (unsigned)((n0 + brow)*GSTR + ks + bkoff)*2);
                ldmx4(bfl, uBl + (unsigned)((n0 + brow)*GSTR + ks + bkoff)*2);
                #pragma unroll
                for (int mi=0;mi<2;mi++)
                    #pragma unroll
                    for (int ni=0;ni<2;ni++){
                        mma16816(acc[mi][ni], afh[mi], bfh[ni*2], bfh[ni*2+1]);
                        mma16816(acc[mi][ni], afh[mi], bfl[ni*2], bfl[ni*2+1]);
                        mma16816(acc[mi][ni], afl[mi], bfh[ni*2], bfh[ni*2+1]);
                    }
            }
            __syncthreads();

            #pragma unroll
            for (int mi=0;mi<2;mi++){
                #pragma unroll
                for (int ni=0;ni<2;ni++){
                    int row = mi*16 + (l >> 2);
                    int col = nbase + n0 + ni*8 + (l & 3)*2;
                    float* gp = g_GpartA + ((size_t)z*BB + row)*JG + col;
                    gp[0] = acc[mi][ni][0];
                    gp[1] = acc[mi][ni][1];
                    gp += 8*JG;
                    gp[0] = acc[mi][ni][2];
                    gp[1] = acc[mi][ni][3];
                }
            }
        }
        gbar(++nb * NCTA);

        // ===== Phase B: cell+attn VECTORIZED (0..31) | convW (32..127) =====
        if (ct < BB){
            const int b = ct;
            float* sg = (float*)(dsm + OFF_SCR);   // 2048 floats (reduced gates)
            float* hh = sg + 2048;                 // 512 floats
            float* sc = hh + 512;                  // 64 floats
            const int len = lens[b];

            // gate reduction: float4 over 512 j-chunks
            #pragma unroll
            for (int v = 0; v < 2; v++){
                int jc = tid + v*256;
                const float4* pe = (const float4*)(g_Gemb + ((size_t)t*BB + b)*JG) + jc;
                float4 s4 = *pe;
                #pragma unroll
                for (int zz=0; zz<8; zz++){
                    float4 p = *((const float4*)(g_GpartA + ((size_t)zz*BB + b)*JG) + jc);
                    s4.x += p.x; s4.y += p.y; s4.z += p.z; s4.w += p.w;
                }
                #pragma unroll
                for (int zz=0; zz<4; zz++){
                    float4 p = *((const float4*)(g_GpartH + ((size_t)zz*BB + b)*JG) + jc);
                    s4.x += p.x; s4.y += p.y; s4.z += p.z; s4.w += p.w;
                }
                ((float4*)sg)[jc] = s4;
            }
            __syncthreads();

            // LSTM nonlinearity
            #pragma unroll
            for (int rep = 0; rep < 2; rep++){
                int h = tid + rep*256;
                float ig = sigf(sg[h]);
                float fg = sigf(sg[512 + h]);
                float gg = tanhf(sg[1024 + h]);
                float og = sigf(sg[1536 + h]);
                int idx = b*HH + h;
                float c = fg * g_c[idx] + ig * gg;
                g_c[idx] = c;
                float h2 = og * tanhf(c);
                g_h[idx] = h2;
                hh[h] = h2;
                g_XC[b*1024 + h] = h2;
                __nv_bfloat16 hi, lo; bsplit(h2, hi, lo);
                g_Xh[b*KX + 1024 + h] = hi;
                g_Xl[b*KX + 1024 + h] = lo;
            }
            __syncthreads();

            // attention scores (float4)
            {
                const float4* hh4 = (const float4*)hh;
                #pragma unroll
                for (int i = 0; i < 8; i++){
                    int s = w*8 + i;
                    const float4* pr4 = (const float4*)(g_proj + ((size_t)s*BB + b)*HH);
                    float sum = 0.f;
                    #pragma unroll
                    for (int p = 0; p < 4; p++){
                        float4 a = hh4[l + p*32];
                        float4 q = pr4[l + p*32];
                        sum += a.x*q.x + a.y*q.y + a.z*q.z + a.w*q.w;
                    }
                    #pragma unroll
                    for (int off=16; off>0; off>>=1) sum += __shfl_xor_sync(0xffffffffu, sum, off);
                    if (l == 0) sc[s] = (s < len) ? sum : -1e9f;
                }
            }
            __syncthreads();

            if (tid < 32){
                float v0 = sc[tid], v1 = sc[tid+32];
                float m = fmaxf(v0, v1);
                #pragma unroll
                for (int off=16; off>0; off>>=1) m = fmaxf(m, __shfl_xor_sync(0xffffffffu, m, off));
                float e0 = expf(v0 - m), e1 = expf(v1 - m);
                float s = e0 + e1;
                #pragma unroll
                for (int off=16; off>0; off>>=1) s += __shfl_xor_sync(0xffffffffu, s, off);
                float inv = 1.0f / s;
                sc[tid]    = e0 * inv;
                sc[tid+32] = e1 * inv;
            }
            __syncthreads();

            // context (float4, s split in 2 halves; combine via smem)
            {
                float4* part = (float4*)(dsm + OFF_SCR);   // reuse sg region (4KB)
                int chunk = tid & 127;
                int shalf = tid >> 7;
                float4 acc = make_float4(0.f,0.f,0.f,0.f);
                const int sbase = shalf*32;
                #pragma unroll 8
                for (int s0 = 0; s0 < 32; s0++){
                    int s = sbase + s0;
                    float wv = sc[s];
                    float4 e = *((const float4*)(enc + ((size_t)s*BB + b)*HH) + chunk);
                    acc.x = fmaf(wv, e.x, acc.x);
                    acc.y = fmaf(wv, e.y, acc.y);
                    acc.z = fmaf(wv, e.z, acc.z);
                    acc.w = fmaf(wv, e.w, acc.w);
                }
                part[tid] = acc;
                __syncthreads();
                if (tid < 128){
                    float4 p0 = part[tid], p1 = part[tid+128];
                    float4 r = make_float4(p0.x+p1.x, p0.y+p1.y, p0.z+p1.z, p0.w+p1.w);
                    *((float4*)(g_XC + b*1024 + 512) + tid) = r;
                }
            }
        } else {
            unsigned winbase = (unsigned)t * 147456u;
            #pragma unroll
            for (int j = 0; j < 6; j++){
                unsigned i4 = winbase + (unsigned)j*24576u + (unsigned)(ct-32)*256u + tid;
                if (i4 < WF4) convW_item(W_o, i4);
            }
        }
        gbar(++nb * NCTA);

        // ===== Phase C: ah2 b-split 2cols/warp (0..63) | gatesH(t+1) (64..127) =====
        if (ct < 64){
            float* xc = (float*)(dsm + OFF_XC);    // 16 batches = 64KB
            {
                const float4* src = (const float4*)(g_XC + bh*16*1024);
                float4* dst = (float4*)xc;
                #pragma unroll
                for (int i = 0; i < 16; i++) dst[tid + i*256] = src[tid + i*256];
            }
            __syncthreads();
            for (int b = 0; b < 16; b++){
                const float* xb = xc + b*1024;
                float s0 = 0.f, s1 = 0.f;
                #pragma unroll
                for (int q=0;q<32;q++){
                    float xv = xb[l + q*32];
                    s0 += wreg0[q] * xv;
                    s1 += wreg1[q] * xv;
                }
                #pragma unroll
                for (int off=16; off>0; off>>=1){
                    s0 += __shfl_xor_sync(0xffffffffu, s0, off);
                    s1 += __shfl_xor_sync(0xffffffffu, s1, off);
                }
                if (l == 0){
                    int gb = bh*16 + b;
                    int r = t*BB + gb;
                    float v0 = tanhf(s0 + wb0);
                    float v1 = tanhf(s1 + wb1);
                    __nv_bfloat16 hi, lo;
                    bsplit(v0, hi, lo);
                    g_Ah[(size_t)r*HH + c0] = hi;
                    g_Al[(size_t)r*HH + c0] = lo;
                    g_Xh[gb*KX + 512 + c0] = hi;
                    g_Xl[gb*KX + 512 + c0] = lo;
                    bsplit(v1, hi, lo);
                    g_Ah[(size_t)r*HH + c0+1] = hi;
                    g_Al[(size_t)r*HH + c0+1] = lo;
                    g_Xh[gb*KX + 512 + c0+1] = hi;
                    g_Xl[gb*KX + 512 + c0+1] = lo;
                }
            }
        } else if (t + 1 < T1){
            const int z2 = (ct-64) >> 4;
            const int nb2 = ((ct-64) & 15) * 128;
            const unsigned sA = base + OFF_SCR;

            auto issueA = [&](int buf, int ck){
                const int koff = 1024 + z2*128 + ck*64;
                const unsigned uAh = sA + buf*9216;
                const unsigned uAl = uAh + 4608;
                #pragma unroll
                for (int q = 0; q < 2; q++){
                    int i = q*256 + tid;
                    int idx = i & 255; int row = idx >> 3, c8 = idx & 7;
                    const __nv_bfloat16* src = (i < 256 ? g_Xh : g_Xl)
                                               + (size_t)row*KX + koff + c8*8;
                    unsigned dst = (i < 256 ? uAh : uAl) + (unsigned)(row*GSTR + c8*8)*2;
                    cpa16(dst, src);
                }
            };

            float acc[2][2][4];
            #pragma unroll
            for (int mi=0;mi<2;mi++)
                #pragma unroll
                for (int ni=0;ni<2;ni++)
                    #pragma unroll
                    for (int q=0;q<4;q++) acc[mi][ni][q]=0.f;

            issueA(0, 0); CP_COMMIT();
            #pragma unroll
            for (int ck = 0; ck < 2; ck++){
                if (ck == 0){ issueA(1, 1); CP_COMMIT(); CP_WAIT(1); }
                else        { CP_WAIT(0); }
                __syncthreads();
                const unsigned uAh = sA + ck*9216;
                const unsigned uAl = uAh + 4608;
                const unsigned uBh = base + OFF_WHB + ck*36864;
                const unsigned uBl = uBh + 18432;
                #pragma unroll
                for (int ks = 0; ks < 64; ks += 16){
                    unsigned afh[2][4], afl[2][4], bfh[4], bfl[4];
                    #pragma unroll
                    for (int mi=0;mi<2;mi++){
                        ldmx4(afh[mi], uAh + (unsigned)((mi*16 + arow)*GSTR + ks + akoff)*2);
                        ldmx4(afl[mi], uAl + (unsigned)((mi*16 + arow)*GSTR + ks + akoff)*2);
                    }
                    ldmx4(bfh, uBh + (unsigned)((n0 + brow)*GSTR + ks + bkoff)*2);
                    ldmx4(bfl, uBl + (unsigned)((n0 + brow)*GSTR + ks + bkoff)*2);
                    #pragma unroll
                    for (int mi=0;mi<2;mi++)
                        #pragma unroll
                        for (int ni=0;ni<2;ni++){
                            mma16816(acc[mi][ni], afh[mi], bfh[ni*2], bfh[ni*2+1]);
                            mma16816(acc[mi][ni], afh[mi], bfl[ni*2], bfl[ni*2+1]);
                            mma16816(acc[mi][ni], afl[mi], bfh[ni*2], bfh[ni*2+1]);
                        }
                }
                __syncthreads();
            }

            #pragma unroll
            for (int mi=0;mi<2;mi++){
                #pragma unroll
                for (int ni=0;ni<2;ni++){
                    int row = mi*16 + (l >> 2);
                    int col = nb2 + n0 + ni*8 + (l & 3)*2;
                    float* gp = g_GpartH + ((size_t)z2*BB + row)*JG + col;
                    gp[0] = acc[mi][ni][0];
                    gp[1] = acc[mi][ni][1];
                    gp += 8*JG;
                    gp[0] = acc[mi][ni][2];
                    gp[1] = acc[mi][ni][3];
                }
            }
        }
        gbar(++nb * NCTA);
    }
}

// ---------------------------------------------------------------------------
// Vocab GEMM (R13-proven)
// ---------------------------------------------------------------------------
__global__ void __launch_bounds__(256, 2)
k_vocab(const float* __restrict__ b_o, float* __restrict__ logits)
{
    extern __shared__ char vsm[];
    const int tid  = threadIdx.x;
    const int wid  = tid >> 5, lane = tid & 31;
    const int mtile = blockIdx.x;
    const int ntile = blockIdx.y;

    const __nv_bfloat16* Asrc_h = g_Ah + (size_t)mtile*128*HH;
    const __nv_bfloat16* Asrc_l = g_Al + (size_t)mtile*128*HH;
    const __nv_bfloat16* Bsrc_h = g_Wh + (size_t)ntile*64*HH;
    const __nv_bfloat16* Bsrc_l = g_Wl + (size_t)ntile*64*HH;

    const unsigned base = smem_u32(vsm);
    const unsigned uAh = base;
    const unsigned uAl = base + 20480;
    const unsigned uBh = base + 40960;
    const unsigned uBl = base + 51200;

    auto issue = [&](int buf, int ch){
        const int k0 = ch*32;
        const unsigned a_h = uAh + buf*10240;
        const unsigned a_l = uAl + buf*10240;
        const unsigned b_h = uBh + buf*5120;
        const unsigned b_l = uBl + buf*5120;
        #pragma unroll
        for (int q = 0; q < 6; q++){
            int i = q*256 + tid;
            if (i < 1024){
                int j = i & 511; int r = j >> 2, c8 = (j & 3)*8;
                const __nv_bfloat16* src = (i < 512 ? Asrc_h : Asrc_l)
                                           + (size_t)r*HH + k0 + c8;
                unsigned dst = (i < 512 ? a_h : a_l) + (unsigned)(r*VK_STR + c8)*2;
                cpa16(dst, src);
            } else {
                int j = (i - 1024) & 255; int r = j >> 2, c8 = (j & 3)*8;
                const __nv_bfloat16* src = (i < 1280 ? Bsrc_h : Bsrc_l)
                                           + (size_t)r*HH + k0 + c8;
                unsigned dst = (i < 1280 ? b_h : b_l) + (unsigned)(r*VK_STR + c8)*2;
                cpa16(dst, src);
            }
        }
    };

    float acc[2][4][4];
    #pragma unroll
    for (int mi=0;mi<2;mi++)
        #pragma unroll
        for (int ni=0;ni<4;ni++)
            #pragma unroll
            for (int q=0;q<4;q++) acc[mi][ni][q]=0.f;

    const int m0 = (wid & 3) * 32;
    const int n0 = (wid >> 2) * 32;
    const int arow  = (lane & 7) + ((lane >> 3) & 1) * 8;
    const int akoff = (lane >> 4) * 8;
    const int brow  = (lane & 7) + ((lane >> 4) & 1) * 8;
    const int bkoff = ((lane >> 3) & 1) * 8;

    issue(0, 0); CP_COMMIT();
    const int NCH = 16;
    for (int ch = 0; ch < NCH; ch++){
        int buf = ch & 1;
        if (ch + 1 < NCH){ issue(buf ^ 1, ch + 1); CP_COMMIT(); CP_WAIT(1); }
        else             { CP_WAIT(0); }
        __syncthreads();
        const unsigned a_h = uAh + buf*10240;
        const unsigned a_l = uAl + buf*10240;
        const unsigned b_h = uBh + buf*5120;
        const unsigned b_l = uBl + buf*5120;

        unsigned afh[2][2][4], afl[2][2][4], bfh[2][2][4], bfl[2][2][4];
        #pragma unroll
        for (int s2 = 0; s2 < 2; s2++){
            const int ks = s2*16;
            #pragma unroll
            for (int mi=0;mi<2;mi++){
                ldmx4(afh[s2][mi], a_h + (unsigned)((m0 + mi*16 + arow)*VK_STR + ks + akoff)*2);
                ldmx4(afl[s2][mi], a_l + (unsigned)((m0 + mi*16 + arow)*VK_STR + ks + akoff)*2);
            }
            #pragma unroll
            for (int g=0; g<2; g++){
                ldmx4(bfh[s2][g], b_h + (unsigned)((n0 + g*16 + brow)*VK_STR + ks + bkoff)*2);
                ldmx4(bfl[s2][g], b_l + (unsigned)((n0 + g*16 + brow)*VK_STR + ks + bkoff)*2);
            }
        }
        #pragma unroll
        for (int s2 = 0; s2 < 2; s2++)
            #pragma unroll
            for (int mi=0;mi<2;mi++)
                #pragma unroll
                for (int ni=0;ni<4;ni++){
                    unsigned h0 = bfh[s2][ni>>1][(ni&1)*2], h1 = bfh[s2][ni>>1][(ni&1)*2+1];
                    unsigned l0 = bfl[s2][ni>>1][(ni&1)*2], l1 = bfl[s2][ni>>1][(ni&1)*2+1];
                    mma16816(acc[mi][ni], afh[s2][mi], h0, h1);
                    mma16816(acc[mi][ni], afh[s2][mi], l0, l1);
                    mma16816(acc[mi][ni], afl[s2][mi], h0, h1);
                }
        __syncthreads();
    }

    #pragma unroll
    for (int mi=0;mi<2;mi++){
        #pragma unroll
        for (int ni=0;ni<4;ni++){
            int row = mtile*128 + m0 + mi*16 + (lane >> 2);
            int col = ntile*64  + n0 + ni*8  + (lane & 3)*2;
            float bia0 = b_o[col], bia1 = b_o[col+1];
            if (row < T1*BB){
                float* o = logits + (size_t)row*VV + col;
                o[0] = acc[mi][ni][0] + bia0;
                o[1] = acc[mi][ni][1] + bia1;
            }
            if (row + 8 < T1*BB){
                float* o = logits + (size_t)(row+8)*VV + col;
                o[0] = acc[mi][ni][2] + bia0;
                o[1] = acc[mi][ni][3] + bia1;
            }
        }
    }
}

// ---------------------------------------------------------------------------
// Online log-softmax + argmax : 512 threads, float4 (R13-proven)
// ---------------------------------------------------------------------------
__global__ void __launch_bounds__(512)
k_lsm(float* __restrict__ logits)
{
    __shared__ float ms[512], ss[512];
    __shared__ int   ii[512];
    const int row = blockIdx.x;
    const int tid = threadIdx.x;
    float* x = logits + (size_t)row * VV;
    const float4* x4 = (const float4*)x;
    const int N4 = VV/4;

    float4 v0 = x4[tid];
    float m = v0.x; int mi = tid*4; float s = 1.f;
    {
        float vals[3] = {v0.y, v0.z, v0.w};
        #pragma unroll
        for (int j=0;j<3;j++){
            float v = vals[j];
            if (v > m){ s = s*fexp(m - v) + 1.f; m = v; mi = tid*4 + j + 1; }
            else        s += fexp(v - m);
        }
    }
    for (int i4 = tid + 512; i4 < N4; i4 += 512){
        float4 v4 = x4[i4];
        float vals[4] = {v4.x, v4.y, v4.z, v4.w};
        #pragma unroll
        for (int j=0;j<4;j++){
            float v = vals[j];
            if (v > m){ s = s*fexp(m - v) + 1.f; m = v; mi = i4*4 + j; }
            else        s += fexp(v - m);
        }
    }
    ms[tid]=m; ss[tid]=s; ii[tid]=mi;
    __syncthreads();
    for (int st = 256; st > 0; st >>= 1){
        if (tid < st){
            float m1=ms[tid], s1=ss[tid]; int i1=ii[tid];
            float m2=ms[tid+st], s2=ss[tid+st]; int i2=ii[tid+st];
            if (m2 > m1)      { ms[tid]=m2; ss[tid]=s1*fexp(m1-m2)+s2; ii[tid]=i2; }
            else if (m2 < m1) { ss[tid]=s1+s2*fexp(m2-m1); }
            else              { ss[tid]=s1+s2; ii[tid]=min(i1,i2); }
        }
        __syncthreads();
    }
    float lse = ms[0] + logf(ss[0]);
    if (tid == 0) g_argmax[row] = ii[0];

    float4* xw = (float4*)x;
    for (int i4 = tid; i4 < N4; i4 += 512){
        float4 v4 = xw[i4];
        v4.x -= lse; v4.y -= lse; v4.z -= lse; v4.w -= lse;
        xw[i4] = v4;
    }
}

__global__ void k_tail_f(float* __restrict__ out)
{
    int r = blockIdx.x*blockDim.x + threadIdx.x;
    if (r < T1*BB) out[TBV + r] = (float)g_argmax[r];
}
__global__ void k_tail_i(int* __restrict__ out)
{
    int r = blockIdx.x*blockDim.x + threadIdx.x;
    if (r < T1*BB) out[r] = g_argmax[r];
}

// ---------------------------------------------------------------------------
extern "C" void kernel_launch(void* const* d_in, const int* in_sizes, int n_in,
                              void* d_out, int out_size)
{
    const int*   tgt   = (const int*)  d_in[0];
    const int*   lens  = (const int*)  d_in[1];
    const float* enc   = (const float*)d_in[2];
    const float* h0    = (const float*)d_in[3];
    const float* c0    = (const float*)d_in[4];
    const float* emb   = (const float*)d_in[5];
    const float* W_ih  = (const float*)d_in[6];
    const float* W_hh  = (const float*)d_in[7];
    const float* b_ih  = (const float*)d_in[8];
    const float* b_hh  = (const float*)d_in[9];
    const float* W_a   = (const float*)d_in[10];
    const float* W_c   = (const float*)d_in[11];
    const float* b_c   = (const float*)d_in[12];
    const float* W_o   = (const float*)d_in[13];
    const float* b_o   = (const float*)d_in[14];

    float *p_lg = nullptr;
    cudaGetSymbolAddress((void**)&p_lg, g_logits);

    const bool big = (size_t)out_size >= TBV;
    float* logits = big ? (float*)d_out : p_lg;

    cudaFuncSetAttribute(k_loop,   cudaFuncAttributeMaxDynamicSharedMemorySize, 131072);
    cudaFuncSetAttribute(k_gh0,    cudaFuncAttributeMaxDynamicSharedMemorySize, 2*ABUF);
    cudaFuncSetAttribute(k_vocab,  cudaFuncAttributeMaxDynamicSharedMemorySize, 61440);
    cudaFuncSetAttribute(k_hmm2,   cudaFuncAttributeMaxDynamicSharedMemorySize, 61440);

    // prologue
    k_convall<<<4928, 256>>>(tgt, emb, W_ih, W_hh, enc, W_a, h0, c0);
    k_hmm2<<<384, 256, 61440>>>(b_ih, b_hh);
    k_gh0<<<64, 256, 2*ABUF>>>();

    // persistent recurrent loop
    k_loop<<<NCTA, 256, 131072>>>(lens, enc, W_c, b_c, W_o);

    // vocab projection + log-softmax
    k_vocab<<<dim3(8, 500), 256, 61440>>>(b_o, logits);
    k_lsm<<<T1*BB, 512>>>(logits);

    if (big && (size_t)out_size >= TBV + (size_t)T1*BB) {
        k_tail_f<<<4, 256>>>((float*)d_out);
    } else if (!big) {
        k_tail_i<<<4, 256>>>((int*)d_out);
    }
}